// round 6
// baseline (speedup 1.0000x reference)
#include <cuda_runtime.h>
#include <cuda_bf16.h>
#include <math.h>
#include <stdint.h>

// ---------------- problem constants ----------------
#define N_NODES   19385
#define N_EDGES   1200000
#define GNN_DIM   256
#define HEAD_DIM  512
#define EXPAND    4
#define N_CLASSES 3
#define N_GENES   6640
#define N_RES     6
#define BATCH     2048
#define FF_DIM    (HEAD_DIM * EXPAND)    // 2048
#define BIL_DIM   (N_CLASSES * HEAD_DIM) // 1536

// ---------------- fp32 scratch ----------------
__device__ float g_aggrc[(size_t)BATCH * GNN_DIM];   // compact aggregation (2 MB)
__device__ int   g_slot[N_NODES];                    // node -> compact slot (-1 = unused)
__device__ float g_Wc1[GNN_DIM * GNN_DIM];
__device__ float g_Wc2[GNN_DIM * GNN_DIM];
__device__ float g_bc[GNN_DIM];
__device__ float g_h[(size_t)BATCH * HEAD_DIM];

// ---------------- bf16 split scratch (hi/lo pairs) ----------------
__device__ __nv_bfloat16 g_perth[(size_t)BATCH * GNN_DIM];
__device__ __nv_bfloat16 g_pertl[(size_t)BATCH * GNN_DIM];
__device__ __nv_bfloat16 g_xnh[(size_t)BATCH * HEAD_DIM];
__device__ __nv_bfloat16 g_xnl[(size_t)BATCH * HEAD_DIM];
__device__ __nv_bfloat16 g_acth[(size_t)BATCH * FF_DIM];
__device__ __nv_bfloat16 g_actl[(size_t)BATCH * FF_DIM];
__device__ __nv_bfloat16 g_hsh[(size_t)BATCH * HEAD_DIM];
__device__ __nv_bfloat16 g_hsl[(size_t)BATCH * HEAD_DIM];
__device__ __nv_bfloat16 g_projh[(size_t)BATCH * BIL_DIM];
__device__ __nv_bfloat16 g_projl[(size_t)BATCH * BIL_DIM];
// weight splits
__device__ __nv_bfloat16 g_Winh[GNN_DIM * HEAD_DIM];
__device__ __nv_bfloat16 g_Winl[GNN_DIM * HEAD_DIM];
__device__ __nv_bfloat16 g_W1h[(size_t)N_RES * HEAD_DIM * FF_DIM];
__device__ __nv_bfloat16 g_W1l[(size_t)N_RES * HEAD_DIM * FF_DIM];
__device__ __nv_bfloat16 g_W2h[(size_t)N_RES * FF_DIM * HEAD_DIM];
__device__ __nv_bfloat16 g_W2l[(size_t)N_RES * FF_DIM * HEAD_DIM];
__device__ __nv_bfloat16 g_bilh[HEAD_DIM * BIL_DIM];
__device__ __nv_bfloat16 g_bill[HEAD_DIM * BIL_DIM];
__device__ __nv_bfloat16 g_oeh[(size_t)N_GENES * HEAD_DIM];
__device__ __nv_bfloat16 g_oel[(size_t)N_GENES * HEAD_DIM];

// ---------------- helpers ----------------
__device__ __forceinline__ float gelu_exact(float v) {
    return 0.5f * v * (1.0f + erff(v * 0.70710678118654752f));
}
__device__ __forceinline__ void split2(float x, __nv_bfloat16& h, __nv_bfloat16& l) {
    h = __float2bfloat16_rn(x);
    l = __float2bfloat16_rn(x - __bfloat162float(h));
}
__device__ __forceinline__ uint32_t smem_u32(const void* p) {
    return (uint32_t)__cvta_generic_to_shared(p);
}
__device__ __forceinline__ void cp16(uint32_t dst, const void* src, bool pred) {
    int sz = pred ? 16 : 0;
    asm volatile("cp.async.cg.shared.global [%0], [%1], 16, %2;\n"
                 :: "r"(dst), "l"(src), "r"(sz));
}
__device__ __forceinline__ void ldm_x4(uint32_t* r, uint32_t addr) {
    asm volatile("ldmatrix.sync.aligned.m8n8.x4.shared.b16 {%0,%1,%2,%3}, [%4];"
                 : "=r"(r[0]), "=r"(r[1]), "=r"(r[2]), "=r"(r[3]) : "r"(addr));
}
__device__ __forceinline__ void ldm_x4_t(uint32_t* r, uint32_t addr) {
    asm volatile("ldmatrix.sync.aligned.m8n8.x4.trans.shared.b16 {%0,%1,%2,%3}, [%4];"
                 : "=r"(r[0]), "=r"(r[1]), "=r"(r[2]), "=r"(r[3]) : "r"(addr));
}
#define MMA_BF16(D, A, B)                                                   \
    asm volatile(                                                           \
        "mma.sync.aligned.m16n8k16.row.col.f32.bf16.bf16.f32 "              \
        "{%0,%1,%2,%3},{%4,%5,%6,%7},{%8,%9},{%0,%1,%2,%3};"                \
        : "+f"((D)[0]), "+f"((D)[1]), "+f"((D)[2]), "+f"((D)[3])            \
        : "r"((A)[0]), "r"((A)[1]), "r"((A)[2]), "r"((A)[3]),               \
          "r"((B)[0]), "r"((B)[1]))

// ---------------- zero compact scratch + slot init ----------------
__global__ void zero_kernel() {
    int stride = gridDim.x * blockDim.x;
    int tid = blockIdx.x * blockDim.x + threadIdx.x;
    int total4 = BATCH * (GNN_DIM / 4);       // 131072
    float4* a4 = reinterpret_cast<float4*>(g_aggrc);
    for (int i = tid; i < total4; i += stride)
        a4[i] = make_float4(0.f, 0.f, 0.f, 0.f);
    for (int i = tid; i < N_NODES; i += stride)
        g_slot[i] = -1;
}

// ---------------- claim compact slots for needed nodes ----------------
__global__ void mark_kernel(const int* __restrict__ idx) {
    int b = blockIdx.x * blockDim.x + threadIdx.x;
    if (b < BATCH) {
        int n = idx[b];
        if (n >= 0) atomicCAS(&g_slot[n], -1, b);   // slot = first claiming batch row
    }
}

// ---------------- filtered edge scatter-add into compact buffer ----------------
__global__ void edge_kernel(const int* __restrict__ ei, const float* __restrict__ ew,
                            const float* __restrict__ x0) {
    const int lane = threadIdx.x & 31;
    const int warp = (blockIdx.x * blockDim.x + threadIdx.x) >> 5;
    const int e0 = warp * 32;
    if (e0 >= N_EDGES) return;
    const int e = e0 + lane;
    int sl = -1, s = 0; float w = 0.f;
    if (e < N_EDGES) {
        int d = ei[N_EDGES + e];
        sl = g_slot[d];
        if (sl >= 0) { s = ei[e]; w = ew[e]; }
    }
    unsigned mask = __ballot_sync(0xffffffffu, sl >= 0);
    while (mask) {
        int b = __ffs(mask) - 1; mask &= (mask - 1);
        int   ss = __shfl_sync(0xffffffffu, s, b);
        int   dd = __shfl_sync(0xffffffffu, sl, b);
        float ww = __shfl_sync(0xffffffffu, w, b);
        const float4* xr = reinterpret_cast<const float4*>(x0 + (size_t)ss * GNN_DIM);
        float* ar = g_aggrc + (size_t)dd * GNN_DIM;
        #pragma unroll
        for (int i = 0; i < 2; i++) {
            int c = lane + i * 32;
            float4 v = xr[c];
            asm volatile("red.global.add.v4.f32 [%0], {%1,%2,%3,%4};"
                         :: "l"(ar + c * 4), "f"(v.x * ww), "f"(v.y * ww),
                            "f"(v.z * ww), "f"(v.w * ww) : "memory");
        }
    }
}

// ---------------- fold message-passing weights ----------------
__global__ void wc_kernel(const float* __restrict__ Wr, const float* __restrict__ Wn,
                          const float* __restrict__ Wp) {
    int i = blockIdx.x, j = threadIdx.x;
    __shared__ float r[GNN_DIM], nn[GNN_DIM];
    r[j]  = Wr[i * GNN_DIM + j] + (i == j ? 1.f : 0.f);
    nn[j] = Wn[i * GNN_DIM + j];
    __syncthreads();
    float a1 = 0.f, a2 = 0.f;
    #pragma unroll 4
    for (int k = 0; k < GNN_DIM; k++) {
        float wp = Wp[k * GNN_DIM + j];
        a1 += r[k] * wp; a2 += nn[k] * wp;
    }
    g_Wc1[i * GNN_DIM + j] = a1;
    g_Wc2[i * GNN_DIM + j] = a2;
}

__global__ void bc_kernel(const float* __restrict__ bmp, const float* __restrict__ Wp,
                          const float* __restrict__ bpost) {
    int j = threadIdx.x;
    float a = bpost[j];
    #pragma unroll 4
    for (int k = 0; k < GNN_DIM; k++)
        a += bmp[k] * Wp[k * GNN_DIM + j];
    g_bc[j] = a;
}

// ---------------- per-batch-row node transform -> split pert ----------------
__global__ void pert_kernel(const int* __restrict__ idx, const float* __restrict__ x0,
                            const float* __restrict__ fb) {
    constexpr int RPB = 8;
    __shared__ float xr[RPB][GNN_DIM];
    __shared__ float ar[RPB][GNN_DIM];
    __shared__ int   ns[RPB], sl[RPB];
    int j = threadIdx.x;
    int b0 = blockIdx.x * RPB;
    if (j < RPB) {
        int n = idx[b0 + j];
        ns[j] = n;
        sl[j] = (n >= 0) ? g_slot[n] : 0;   // marked earlier -> >= 0
    }
    __syncthreads();
    #pragma unroll
    for (int r = 0; r < RPB; r++) {
        int n = ns[r]; int sn = (n < 0) ? 0 : n;
        xr[r][j] = x0[(size_t)sn * GNN_DIM + j];
        ar[r][j] = g_aggrc[(size_t)sl[r] * GNN_DIM + j];
    }
    __syncthreads();
    float acc[RPB];
    #pragma unroll
    for (int r = 0; r < RPB; r++) acc[r] = g_bc[j];
    for (int k = 0; k < GNN_DIM; k++) {
        float w1 = g_Wc1[k * GNN_DIM + j];
        float w2 = g_Wc2[k * GNN_DIM + j];
        #pragma unroll
        for (int r = 0; r < RPB; r++)
            acc[r] += xr[r][k] * w1 + ar[r][k] * w2;
    }
    float fbj = fb[j];
    #pragma unroll
    for (int r = 0; r < RPB; r++) {
        float v = (ns[r] >= 0) ? acc[r] : fbj;
        __nv_bfloat16 h, l; split2(v, h, l);
        g_perth[(size_t)(b0 + r) * GNN_DIM + j] = h;
        g_pertl[(size_t)(b0 + r) * GNN_DIM + j] = l;
    }
}

// ---------------- layernorm -> split xn ----------------
__global__ void ln_kernel(const float* __restrict__ hbuf, const float* __restrict__ g,
                          const float* __restrict__ bb) {
    int row = blockIdx.x;
    const float* x = hbuf + (size_t)row * HEAD_DIM;
    int tid = threadIdx.x;   // 128
    float v[4]; float s = 0.f, s2 = 0.f;
    #pragma unroll
    for (int i = 0; i < 4; i++) {
        v[i] = x[tid + i * 128];
        s += v[i]; s2 += v[i] * v[i];
    }
    #pragma unroll
    for (int o = 16; o; o >>= 1) {
        s  += __shfl_down_sync(0xffffffffu, s, o);
        s2 += __shfl_down_sync(0xffffffffu, s2, o);
    }
    __shared__ float ss[4], ss2[4];
    if ((tid & 31) == 0) { ss[tid >> 5] = s; ss2[tid >> 5] = s2; }
    __syncthreads();
    s  = ss[0] + ss[1] + ss[2] + ss[3];
    s2 = ss2[0] + ss2[1] + ss2[2] + ss2[3];
    float mu  = s * (1.f / HEAD_DIM);
    float var = s2 * (1.f / HEAD_DIM) - mu * mu;
    float rs  = rsqrtf(var + 1e-5f);
    #pragma unroll
    for (int i = 0; i < 4; i++) {
        int j = tid + i * 128;
        float o = (v[i] - mu) * rs * g[j] + bb[j];
        __nv_bfloat16 hh, ll; split2(o, hh, ll);
        g_xnh[(size_t)row * HEAD_DIM + j] = hh;
        g_xnl[(size_t)row * HEAD_DIM + j] = ll;
    }
}

// ---------------- fp32 -> bf16 hi/lo split (weights) ----------------
__global__ void split_kernel(const float* __restrict__ src,
                             __nv_bfloat16* __restrict__ dh,
                             __nv_bfloat16* __restrict__ dl, int n4) {
    int stride = gridDim.x * blockDim.x;
    for (int i = blockIdx.x * blockDim.x + threadIdx.x; i < n4; i += stride) {
        float4 v = reinterpret_cast<const float4*>(src)[i];
        __nv_bfloat16 h0, l0, h1, l1, h2, l2, h3, l3;
        split2(v.x, h0, l0); split2(v.y, h1, l1);
        split2(v.z, h2, l2); split2(v.w, h3, l3);
        __nv_bfloat162* ph = reinterpret_cast<__nv_bfloat162*>(dh) + i * 2;
        __nv_bfloat162* pl = reinterpret_cast<__nv_bfloat162*>(dl) + i * 2;
        ph[0] = __nv_bfloat162{h0, h1}; ph[1] = __nv_bfloat162{h2, h3};
        pl[0] = __nv_bfloat162{l0, l1}; pl[1] = __nv_bfloat162{l2, l3};
    }
}

// ================= bf16x3 tensor-core GEMM (large tiles) =================
// C[M,N] = (Ah+Al)[M,K] @ (Bh+Bl); D += Ah*Bh + Al*Bh + Ah*Bl.
// Tiles: BM x BN x 32 with 8 warps in (BM/64) x (BN/64) grid; warp tile 64x64.
// TRANSB: B source is [N,K]; else [K,N]. N ragged only with TRANSB.
template<int BM, int BN, bool TRANSB>
struct GCfg {
    static constexpr int ASTR = 40;                     // [row][k] stride, BK=32
    static constexpr int BSTR = BN + 8;                 // [k][n] stride
    static constexpr int AE = BM * ASTR;
    static constexpr int BE = TRANSB ? BN * ASTR : 32 * BSTR;
    static constexpr int STAGE_E = 2 * AE + 2 * BE;
    static constexpr int SMEM = STAGE_E * 2 * 2;        // 2 stages, bf16
};

template<int BM, int BN, bool TRANSB>
__device__ __forceinline__ void load_stage(
    __nv_bfloat16* sm, int stage, int k0,
    const __nv_bfloat16* Ah, const __nv_bfloat16* Al,
    const __nv_bfloat16* Bh, const __nv_bfloat16* Bl,
    int N, int K, int crow, int ccol, int tid)
{
    using C = GCfg<BM, BN, TRANSB>;
    __nv_bfloat16* base = sm + stage * C::STAGE_E;
    __nv_bfloat16* As_h = base;
    __nv_bfloat16* As_l = base + C::AE;
    __nv_bfloat16* Bs_h = base + 2 * C::AE;
    __nv_bfloat16* Bs_l = base + 2 * C::AE + C::BE;
    #pragma unroll
    for (int i = 0; i < BM / 64; i++) {
        int q = tid + i * 256;
        int row = q >> 2, c8 = (q & 3) * 8;
        size_t g = (size_t)(crow + row) * K + k0 + c8;
        uint32_t so = row * C::ASTR + c8;
        cp16(smem_u32(As_h + so), Ah + g, true);
        cp16(smem_u32(As_l + so), Al + g, true);
    }
    if (!TRANSB) {
        #pragma unroll
        for (int i = 0; i < BN / 64; i++) {
            int q = tid + i * 256;
            int row = q / (BN / 8), c8 = (q % (BN / 8)) * 8;
            size_t g = (size_t)(k0 + row) * N + ccol + c8;
            uint32_t so = row * C::BSTR + c8;
            cp16(smem_u32(Bs_h + so), Bh + g, true);
            cp16(smem_u32(Bs_l + so), Bl + g, true);
        }
    } else {
        #pragma unroll
        for (int i = 0; i < BN / 64; i++) {
            int q = tid + i * 256;
            int row = q >> 2, c8 = (q & 3) * 8;
            bool ok = (ccol + row) < N;
            size_t g = ok ? ((size_t)(ccol + row) * K + k0 + c8) : 0;
            uint32_t so = row * C::ASTR + c8;
            cp16(smem_u32(Bs_h + so), Bh + g, ok);
            cp16(smem_u32(Bs_l + so), Bl + g, ok);
        }
    }
}

template<int ASTR>
__device__ __forceinline__ void load_afrag(uint32_t a[4][4], const __nv_bfloat16* As,
                                           int warpM, int lane, int kk) {
    int lrow = warpM + (lane & 15);
    int lcol = kk + ((lane >> 4) << 3);
    #pragma unroll
    for (int mt = 0; mt < 4; mt++)
        ldm_x4(a[mt], smem_u32(As + (lrow + mt * 16) * ASTR + lcol));
}

template<int BN, bool TRANSB>
__device__ __forceinline__ void load_bfrag(uint32_t b[8][2], const __nv_bfloat16* Bs,
                                           int warpN, int lane, int kk) {
    using C = GCfg<128, BN, TRANSB>;   // strides independent of BM
    int j = lane >> 3, r8 = lane & 7;
    if (!TRANSB) {
        int krow = kk + r8 + ((j & 1) << 3);
        #pragma unroll
        for (int np = 0; np < 4; np++) {
            int ncol = warpN + np * 16 + ((j >> 1) << 3);
            uint32_t r[4];
            ldm_x4_t(r, smem_u32(Bs + krow * C::BSTR + ncol));
            b[np * 2][0] = r[0]; b[np * 2][1] = r[1];
            b[np * 2 + 1][0] = r[2]; b[np * 2 + 1][1] = r[3];
        }
    } else {
        int kcol = kk + ((j & 1) << 3);
        #pragma unroll
        for (int np = 0; np < 4; np++) {
            int nrow = warpN + np * 16 + r8 + ((j >> 1) << 3);
            uint32_t r[4];
            ldm_x4(r, smem_u32(Bs + nrow * C::ASTR + kcol));
            b[np * 2][0] = r[0]; b[np * 2][1] = r[1];
            b[np * 2 + 1][0] = r[2]; b[np * 2 + 1][1] = r[3];
        }
    }
}

template<int BM, int BN, bool TRANSB, bool BIAS, bool GELU, bool SPLITOUT, bool RESID>
__global__ void __launch_bounds__(256, 1) gemm_bf3(
    int M, int N, int K,
    const __nv_bfloat16* __restrict__ Ah, const __nv_bfloat16* __restrict__ Al,
    const __nv_bfloat16* __restrict__ Bh, const __nv_bfloat16* __restrict__ Bl,
    const float* __restrict__ bias, float* __restrict__ C,
    __nv_bfloat16* __restrict__ Oh, __nv_bfloat16* __restrict__ Ol)
{
    using CF = GCfg<BM, BN, TRANSB>;
    extern __shared__ __nv_bfloat16 sm[];
    const int tid  = threadIdx.x;
    const int lane = tid & 31;
    const int warp = tid >> 5;
    const int crow = blockIdx.y * BM;
    const int ccol = blockIdx.x * BN;
    constexpr int WNG = BN / 64;
    const int warpM = (warp / WNG) * 64;
    const int warpN = (warp % WNG) * 64;
    const int r = lane >> 2, c = lane & 3;

    float acc[4][8][4];
    #pragma unroll
    for (int mt = 0; mt < 4; mt++)
        #pragma unroll
        for (int nt = 0; nt < 8; nt++)
            #pragma unroll
            for (int i = 0; i < 4; i++) acc[mt][nt][i] = 0.f;

    const int KT = K / 32;
    load_stage<BM, BN, TRANSB>(sm, 0, 0, Ah, Al, Bh, Bl, N, K, crow, ccol, tid);
    asm volatile("cp.async.commit_group;" ::: "memory");

    for (int kt = 0; kt < KT; kt++) {
        if (kt + 1 < KT) {
            load_stage<BM, BN, TRANSB>(sm, (kt + 1) & 1, (kt + 1) * 32,
                                       Ah, Al, Bh, Bl, N, K, crow, ccol, tid);
            asm volatile("cp.async.commit_group;" ::: "memory");
            asm volatile("cp.async.wait_group 1;" ::: "memory");
        } else {
            asm volatile("cp.async.wait_group 0;" ::: "memory");
        }
        __syncthreads();

        const int st = kt & 1;
        const __nv_bfloat16* base = sm + st * CF::STAGE_E;
        const __nv_bfloat16* As_h = base;
        const __nv_bfloat16* As_l = base + CF::AE;
        const __nv_bfloat16* Bs_h = base + 2 * CF::AE;
        const __nv_bfloat16* Bs_l = base + 2 * CF::AE + CF::BE;

        #pragma unroll
        for (int ks = 0; ks < 2; ks++) {
            const int kk = ks * 16;
            uint32_t ah[4][4], al[4][4], bh[8][2], bl[8][2];
            load_afrag<CF::ASTR>(ah, As_h, warpM, lane, kk);
            load_bfrag<BN, TRANSB>(bh, Bs_h, warpN, lane, kk);
            #pragma unroll
            for (int mt = 0; mt < 4; mt++)
                #pragma unroll
                for (int nt = 0; nt < 8; nt++)
                    MMA_BF16(acc[mt][nt], ah[mt], bh[nt]);
            load_afrag<CF::ASTR>(al, As_l, warpM, lane, kk);
            #pragma unroll
            for (int mt = 0; mt < 4; mt++)
                #pragma unroll
                for (int nt = 0; nt < 8; nt++)
                    MMA_BF16(acc[mt][nt], al[mt], bh[nt]);
            load_bfrag<BN, TRANSB>(bl, Bs_l, warpN, lane, kk);
            #pragma unroll
            for (int mt = 0; mt < 4; mt++)
                #pragma unroll
                for (int nt = 0; nt < 8; nt++)
                    MMA_BF16(acc[mt][nt], ah[mt], bl[nt]);
        }
        __syncthreads();
    }

    // ---- epilogue ----
    #pragma unroll
    for (int mt = 0; mt < 4; mt++) {
        #pragma unroll
        for (int nt = 0; nt < 8; nt++) {
            int m0 = crow + warpM + mt * 16;
            int n0 = ccol + warpN + nt * 8;
            #pragma unroll
            for (int half = 0; half < 2; half++) {
                int m = m0 + r + half * 8;
                int n = n0 + c * 2;
                if (n >= N) continue;   // pairs never straddle (N even)
                float v0 = acc[mt][nt][half * 2 + 0];
                float v1 = acc[mt][nt][half * 2 + 1];
                if (BIAS) { v0 += bias[n]; v1 += bias[n + 1]; }
                if (GELU) { v0 = gelu_exact(v0); v1 = gelu_exact(v1); }
                if (RESID) {
                    float2 o = *reinterpret_cast<float2*>(C + (size_t)m * N + n);
                    v0 += o.x; v1 += o.y;
                }
                if (SPLITOUT) {
                    __nv_bfloat16 h0, l0, h1, l1;
                    split2(v0, h0, l0); split2(v1, h1, l1);
                    *reinterpret_cast<__nv_bfloat162*>(Oh + (size_t)m * N + n) =
                        __nv_bfloat162{h0, h1};
                    *reinterpret_cast<__nv_bfloat162*>(Ol + (size_t)m * N + n) =
                        __nv_bfloat162{l0, l1};
                } else {
                    *reinterpret_cast<float2*>(C + (size_t)m * N + n) =
                        make_float2(v0, v1);
                }
            }
        }
    }
}

// ---------------- launch ----------------
extern "C" void kernel_launch(void* const* d_in, const int* in_sizes, int n_in,
                              void* d_out, int out_size) {
    const int*   node_idx  = (const int*)  d_in[0];
    const int*   edge_idx  = (const int*)  d_in[1];
    const float* edge_w    = (const float*)d_in[2];
    const float* frozen    = (const float*)d_in[3];
    const float* W_root    = (const float*)d_in[4];
    const float* W_nbr     = (const float*)d_in[5];
    const float* b_mp      = (const float*)d_in[6];
    const float* W_post    = (const float*)d_in[7];
    const float* b_post    = (const float*)d_in[8];
    const float* fallback  = (const float*)d_in[9];
    const float* W_in      = (const float*)d_in[10];
    const float* b_in      = (const float*)d_in[11];
    const float* ln_g      = (const float*)d_in[12];
    const float* ln_b      = (const float*)d_in[13];
    const float* W1        = (const float*)d_in[14];
    const float* b1        = (const float*)d_in[15];
    const float* W2        = (const float*)d_in[16];
    const float* W_bil     = (const float*)d_in[17];
    const float* out_emb   = (const float*)d_in[18];
    float*       logits    = (float*)d_out;

    float *p_h;
    cudaGetSymbolAddress((void**)&p_h, g_h);
    __nv_bfloat16 *p_perth, *p_pertl, *p_xnh, *p_xnl, *p_acth, *p_actl;
    __nv_bfloat16 *p_hsh, *p_hsl, *p_projh, *p_projl;
    __nv_bfloat16 *p_Winh, *p_Winl, *p_W1h, *p_W1l, *p_W2h, *p_W2l;
    __nv_bfloat16 *p_bilh, *p_bill, *p_oeh, *p_oel;
    cudaGetSymbolAddress((void**)&p_perth, g_perth);
    cudaGetSymbolAddress((void**)&p_pertl, g_pertl);
    cudaGetSymbolAddress((void**)&p_xnh,  g_xnh);
    cudaGetSymbolAddress((void**)&p_xnl,  g_xnl);
    cudaGetSymbolAddress((void**)&p_acth, g_acth);
    cudaGetSymbolAddress((void**)&p_actl, g_actl);
    cudaGetSymbolAddress((void**)&p_hsh,  g_hsh);
    cudaGetSymbolAddress((void**)&p_hsl,  g_hsl);
    cudaGetSymbolAddress((void**)&p_projh, g_projh);
    cudaGetSymbolAddress((void**)&p_projl, g_projl);
    cudaGetSymbolAddress((void**)&p_Winh, g_Winh);
    cudaGetSymbolAddress((void**)&p_Winl, g_Winl);
    cudaGetSymbolAddress((void**)&p_W1h,  g_W1h);
    cudaGetSymbolAddress((void**)&p_W1l,  g_W1l);
    cudaGetSymbolAddress((void**)&p_W2h,  g_W2h);
    cudaGetSymbolAddress((void**)&p_W2l,  g_W2l);
    cudaGetSymbolAddress((void**)&p_bilh, g_bilh);
    cudaGetSymbolAddress((void**)&p_bill, g_bill);
    cudaGetSymbolAddress((void**)&p_oeh,  g_oeh);
    cudaGetSymbolAddress((void**)&p_oel,  g_oel);

    // dynamic-smem opt-in per instantiation
    cudaFuncSetAttribute(gemm_bf3<256,128,false, true,  true,  false, false>,
        cudaFuncAttributeMaxDynamicSharedMemorySize, GCfg<256,128,false>::SMEM);
    cudaFuncSetAttribute(gemm_bf3<256,128,false, true,  true,  true,  false>,
        cudaFuncAttributeMaxDynamicSharedMemorySize, GCfg<256,128,false>::SMEM);
    cudaFuncSetAttribute(gemm_bf3<256,128,false, false, false, false, true>,
        cudaFuncAttributeMaxDynamicSharedMemorySize, GCfg<256,128,false>::SMEM);
    cudaFuncSetAttribute(gemm_bf3<256,128,false, false, false, true,  true>,
        cudaFuncAttributeMaxDynamicSharedMemorySize, GCfg<256,128,false>::SMEM);
    cudaFuncSetAttribute(gemm_bf3<256,128,false, false, false, true,  false>,
        cudaFuncAttributeMaxDynamicSharedMemorySize, GCfg<256,128,false>::SMEM);
    cudaFuncSetAttribute(gemm_bf3<128,256,true,  false, false, false, false>,
        cudaFuncAttributeMaxDynamicSharedMemorySize, GCfg<128,256,true>::SMEM);

    // --- weight splits (bf16 hi/lo) ---
    split_kernel<<<256, 256>>>(W_in,   p_Winh, p_Winl, GNN_DIM * HEAD_DIM / 4);
    split_kernel<<<1024, 256>>>(W1,    p_W1h,  p_W1l,  N_RES * HEAD_DIM * FF_DIM / 4);
    split_kernel<<<1024, 256>>>(W2,    p_W2h,  p_W2l,  N_RES * FF_DIM * HEAD_DIM / 4);
    split_kernel<<<512, 256>>>(W_bil,  p_bilh, p_bill, HEAD_DIM * BIL_DIM / 4);
    split_kernel<<<1024, 256>>>(out_emb, p_oeh, p_oel, N_GENES * HEAD_DIM / 4);

    // --- graph phase (compact slots) ---
    zero_kernel<<<512, 256>>>();
    mark_kernel<<<(BATCH + 255) / 256, 256>>>(node_idx);
    {
        int warps = (N_EDGES + 31) / 32;
        int blocks = (warps + 7) / 8;
        edge_kernel<<<blocks, 256>>>(edge_idx, edge_w, frozen);
    }
    wc_kernel<<<GNN_DIM, GNN_DIM>>>(W_root, W_nbr, W_post);
    bc_kernel<<<1, GNN_DIM>>>(b_mp, W_post, b_post);
    pert_kernel<<<BATCH / 8, GNN_DIM>>>(node_idx, frozen, fallback);

    // --- dense head ---
    // h = gelu(pert @ W_in + b_in)
    {
        dim3 grid(HEAD_DIM / 128, BATCH / 256);
        gemm_bf3<256,128,false, true, true, false, false>
            <<<grid, 256, GCfg<256,128,false>::SMEM>>>(
            BATCH, HEAD_DIM, GNN_DIM, p_perth, p_pertl, p_Winh, p_Winl,
            b_in, p_h, nullptr, nullptr);
    }
    for (int i = 0; i < N_RES; i++) {
        ln_kernel<<<BATCH, 128>>>(p_h, ln_g + (size_t)i * HEAD_DIM,
                                  ln_b + (size_t)i * HEAD_DIM);
        dim3 g1(FF_DIM / 128, BATCH / 256);
        gemm_bf3<256,128,false, true, true, true, false>
            <<<g1, 256, GCfg<256,128,false>::SMEM>>>(
            BATCH, FF_DIM, HEAD_DIM, p_xnh, p_xnl,
            p_W1h + (size_t)i * HEAD_DIM * FF_DIM, p_W1l + (size_t)i * HEAD_DIM * FF_DIM,
            b1 + (size_t)i * FF_DIM, nullptr, p_acth, p_actl);
        dim3 g2(HEAD_DIM / 128, BATCH / 256);
        if (i < N_RES - 1) {
            gemm_bf3<256,128,false, false, false, false, true>
                <<<g2, 256, GCfg<256,128,false>::SMEM>>>(
                BATCH, HEAD_DIM, FF_DIM, p_acth, p_actl,
                p_W2h + (size_t)i * FF_DIM * HEAD_DIM, p_W2l + (size_t)i * FF_DIM * HEAD_DIM,
                nullptr, p_h, nullptr, nullptr);
        } else {
            // last block: residual-add + split h for the bil GEMM (fused)
            gemm_bf3<256,128,false, false, false, true, true>
                <<<g2, 256, GCfg<256,128,false>::SMEM>>>(
                BATCH, HEAD_DIM, FF_DIM, p_acth, p_actl,
                p_W2h + (size_t)i * FF_DIM * HEAD_DIM, p_W2l + (size_t)i * FF_DIM * HEAD_DIM,
                nullptr, p_h, p_hsh, p_hsl);
        }
    }
    // proj = h @ W_bil (split output)
    {
        dim3 grid(BIL_DIM / 128, BATCH / 256);
        gemm_bf3<256,128,false, false, false, true, false>
            <<<grid, 256, GCfg<256,128,false>::SMEM>>>(
            BATCH, BIL_DIM, HEAD_DIM, p_hsh, p_hsl, p_bilh, p_bill,
            nullptr, nullptr, p_projh, p_projl);
    }
    // logits = reshape(proj,[B*3,512]) @ out_emb^T
    {
        dim3 grid((N_GENES + 255) / 256, (BATCH * N_CLASSES) / 128);
        gemm_bf3<128,256,true, false, false, false, false>
            <<<grid, 256, GCfg<128,256,true>::SMEM>>>(
            BATCH * N_CLASSES, N_GENES, HEAD_DIM, p_projh, p_projl, p_oeh, p_oel,
            nullptr, logits, nullptr, nullptr);
    }
}

// round 8
// speedup vs baseline: 1.2133x; 1.2133x over previous
#include <cuda_runtime.h>
#include <cuda_bf16.h>
#include <math.h>
#include <stdint.h>

// ---------------- problem constants ----------------
#define N_NODES   19385
#define N_EDGES   1200000
#define GNN_DIM   256
#define HEAD_DIM  512
#define EXPAND    4
#define N_CLASSES 3
#define N_GENES   6640
#define N_RES     6
#define BATCH     2048
#define FF_DIM    (HEAD_DIM * EXPAND)    // 2048
#define BIL_DIM   (N_CLASSES * HEAD_DIM) // 1536

// ---------------- fp32 scratch ----------------
__device__ float g_aggrc[(size_t)BATCH * GNN_DIM];   // compact aggregation (2 MB)
__device__ int   g_slot[N_NODES];                    // node -> compact slot (-1 = unused)
__device__ float g_Wc1[GNN_DIM * GNN_DIM];
__device__ float g_Wc2[GNN_DIM * GNN_DIM];
__device__ float g_bc[GNN_DIM];
__device__ float g_h[(size_t)BATCH * HEAD_DIM];

// ---------------- bf16 split scratch (hi/lo pairs) ----------------
__device__ __nv_bfloat16 g_perth[(size_t)BATCH * GNN_DIM];
__device__ __nv_bfloat16 g_pertl[(size_t)BATCH * GNN_DIM];
__device__ __nv_bfloat16 g_xnh[(size_t)BATCH * HEAD_DIM];
__device__ __nv_bfloat16 g_xnl[(size_t)BATCH * HEAD_DIM];
__device__ __nv_bfloat16 g_acth[(size_t)BATCH * FF_DIM];
__device__ __nv_bfloat16 g_actl[(size_t)BATCH * FF_DIM];
__device__ __nv_bfloat16 g_hsh[(size_t)BATCH * HEAD_DIM];
__device__ __nv_bfloat16 g_hsl[(size_t)BATCH * HEAD_DIM];
__device__ __nv_bfloat16 g_projh[(size_t)BATCH * BIL_DIM];
__device__ __nv_bfloat16 g_projl[(size_t)BATCH * BIL_DIM];
// weight splits
__device__ __nv_bfloat16 g_Winh[GNN_DIM * HEAD_DIM];
__device__ __nv_bfloat16 g_Winl[GNN_DIM * HEAD_DIM];
__device__ __nv_bfloat16 g_W1h[(size_t)N_RES * HEAD_DIM * FF_DIM];
__device__ __nv_bfloat16 g_W1l[(size_t)N_RES * HEAD_DIM * FF_DIM];
__device__ __nv_bfloat16 g_W2h[(size_t)N_RES * FF_DIM * HEAD_DIM];
__device__ __nv_bfloat16 g_W2l[(size_t)N_RES * FF_DIM * HEAD_DIM];
__device__ __nv_bfloat16 g_bilh[HEAD_DIM * BIL_DIM];
__device__ __nv_bfloat16 g_bill[HEAD_DIM * BIL_DIM];
__device__ __nv_bfloat16 g_oeh[(size_t)N_GENES * HEAD_DIM];
__device__ __nv_bfloat16 g_oel[(size_t)N_GENES * HEAD_DIM];

// ---------------- helpers ----------------
__device__ __forceinline__ float gelu_exact(float v) {
    return 0.5f * v * (1.0f + erff(v * 0.70710678118654752f));
}
__device__ __forceinline__ void split2(float x, __nv_bfloat16& h, __nv_bfloat16& l) {
    h = __float2bfloat16_rn(x);
    l = __float2bfloat16_rn(x - __bfloat162float(h));
}
__device__ __forceinline__ uint32_t smem_u32(const void* p) {
    return (uint32_t)__cvta_generic_to_shared(p);
}
__device__ __forceinline__ void cp16(uint32_t dst, const void* src, bool pred) {
    int sz = pred ? 16 : 0;
    asm volatile("cp.async.cg.shared.global [%0], [%1], 16, %2;\n"
                 :: "r"(dst), "l"(src), "r"(sz));
}
__device__ __forceinline__ void ldm_x4(uint32_t* r, uint32_t addr) {
    asm volatile("ldmatrix.sync.aligned.m8n8.x4.shared.b16 {%0,%1,%2,%3}, [%4];"
                 : "=r"(r[0]), "=r"(r[1]), "=r"(r[2]), "=r"(r[3]) : "r"(addr));
}
__device__ __forceinline__ void ldm_x4_t(uint32_t* r, uint32_t addr) {
    asm volatile("ldmatrix.sync.aligned.m8n8.x4.trans.shared.b16 {%0,%1,%2,%3}, [%4];"
                 : "=r"(r[0]), "=r"(r[1]), "=r"(r[2]), "=r"(r[3]) : "r"(addr));
}
#define MMA_BF16(D, A, B)                                                   \
    asm volatile(                                                           \
        "mma.sync.aligned.m16n8k16.row.col.f32.bf16.bf16.f32 "              \
        "{%0,%1,%2,%3},{%4,%5,%6,%7},{%8,%9},{%0,%1,%2,%3};"                \
        : "+f"((D)[0]), "+f"((D)[1]), "+f"((D)[2]), "+f"((D)[3])            \
        : "r"((A)[0]), "r"((A)[1]), "r"((A)[2]), "r"((A)[3]),               \
          "r"((B)[0]), "r"((B)[1]))

// ---------------- zero compact scratch + slot init ----------------
__global__ void zero_kernel() {
    int stride = gridDim.x * blockDim.x;
    int tid = blockIdx.x * blockDim.x + threadIdx.x;
    int total4 = BATCH * (GNN_DIM / 4);       // 131072
    float4* a4 = reinterpret_cast<float4*>(g_aggrc);
    for (int i = tid; i < total4; i += stride)
        a4[i] = make_float4(0.f, 0.f, 0.f, 0.f);
    for (int i = tid; i < N_NODES; i += stride)
        g_slot[i] = -1;
}

// ---------------- claim compact slots for needed nodes ----------------
__global__ void mark_kernel(const int* __restrict__ idx) {
    int b = blockIdx.x * blockDim.x + threadIdx.x;
    if (b < BATCH) {
        int n = idx[b];
        if (n >= 0) atomicCAS(&g_slot[n], -1, b);   // slot = first claiming batch row
    }
}

// ---------------- filtered edge scatter-add into compact buffer ----------------
__global__ void edge_kernel(const int* __restrict__ ei, const float* __restrict__ ew,
                            const float* __restrict__ x0) {
    const int lane = threadIdx.x & 31;
    const int warp = (blockIdx.x * blockDim.x + threadIdx.x) >> 5;
    const int e0 = warp * 32;
    if (e0 >= N_EDGES) return;
    const int e = e0 + lane;
    int sl = -1, s = 0; float w = 0.f;
    if (e < N_EDGES) {
        int d = ei[N_EDGES + e];
        sl = g_slot[d];
        if (sl >= 0) { s = ei[e]; w = ew[e]; }
    }
    unsigned mask = __ballot_sync(0xffffffffu, sl >= 0);
    while (mask) {
        int b = __ffs(mask) - 1; mask &= (mask - 1);
        int   ss = __shfl_sync(0xffffffffu, s, b);
        int   dd = __shfl_sync(0xffffffffu, sl, b);
        float ww = __shfl_sync(0xffffffffu, w, b);
        const float4* xr = reinterpret_cast<const float4*>(x0 + (size_t)ss * GNN_DIM);
        float* ar = g_aggrc + (size_t)dd * GNN_DIM;
        #pragma unroll
        for (int i = 0; i < 2; i++) {
            int c = lane + i * 32;
            float4 v = xr[c];
            asm volatile("red.global.add.v4.f32 [%0], {%1,%2,%3,%4};"
                         :: "l"(ar + c * 4), "f"(v.x * ww), "f"(v.y * ww),
                            "f"(v.z * ww), "f"(v.w * ww) : "memory");
        }
    }
}

// ---------------- fold message-passing weights ----------------
__global__ void wc_kernel(const float* __restrict__ Wr, const float* __restrict__ Wn,
                          const float* __restrict__ Wp) {
    int i = blockIdx.x, j = threadIdx.x;
    __shared__ float r[GNN_DIM], nn[GNN_DIM];
    r[j]  = Wr[i * GNN_DIM + j] + (i == j ? 1.f : 0.f);
    nn[j] = Wn[i * GNN_DIM + j];
    __syncthreads();
    float a1 = 0.f, a2 = 0.f;
    #pragma unroll 4
    for (int k = 0; k < GNN_DIM; k++) {
        float wp = Wp[k * GNN_DIM + j];
        a1 += r[k] * wp; a2 += nn[k] * wp;
    }
    g_Wc1[i * GNN_DIM + j] = a1;
    g_Wc2[i * GNN_DIM + j] = a2;
}

__global__ void bc_kernel(const float* __restrict__ bmp, const float* __restrict__ Wp,
                          const float* __restrict__ bpost) {
    int j = threadIdx.x;
    float a = bpost[j];
    #pragma unroll 4
    for (int k = 0; k < GNN_DIM; k++)
        a += bmp[k] * Wp[k * GNN_DIM + j];
    g_bc[j] = a;
}

// ---------------- per-batch-row node transform -> split pert ----------------
__global__ void pert_kernel(const int* __restrict__ idx, const float* __restrict__ x0,
                            const float* __restrict__ fb) {
    constexpr int RPB = 8;
    __shared__ float xr[RPB][GNN_DIM];
    __shared__ float ar[RPB][GNN_DIM];
    __shared__ int   ns[RPB], sl[RPB];
    int j = threadIdx.x;
    int b0 = blockIdx.x * RPB;
    if (j < RPB) {
        int n = idx[b0 + j];
        ns[j] = n;
        sl[j] = (n >= 0) ? g_slot[n] : 0;
    }
    __syncthreads();
    #pragma unroll
    for (int r = 0; r < RPB; r++) {
        int n = ns[r]; int sn = (n < 0) ? 0 : n;
        xr[r][j] = x0[(size_t)sn * GNN_DIM + j];
        ar[r][j] = g_aggrc[(size_t)sl[r] * GNN_DIM + j];
    }
    __syncthreads();
    float acc[RPB];
    #pragma unroll
    for (int r = 0; r < RPB; r++) acc[r] = g_bc[j];
    for (int k = 0; k < GNN_DIM; k++) {
        float w1 = g_Wc1[k * GNN_DIM + j];
        float w2 = g_Wc2[k * GNN_DIM + j];
        #pragma unroll
        for (int r = 0; r < RPB; r++)
            acc[r] += xr[r][k] * w1 + ar[r][k] * w2;
    }
    float fbj = fb[j];
    #pragma unroll
    for (int r = 0; r < RPB; r++) {
        float v = (ns[r] >= 0) ? acc[r] : fbj;
        __nv_bfloat16 h, l; split2(v, h, l);
        g_perth[(size_t)(b0 + r) * GNN_DIM + j] = h;
        g_pertl[(size_t)(b0 + r) * GNN_DIM + j] = l;
    }
}

// ---------------- layernorm -> split xn ----------------
__global__ void ln_kernel(const float* __restrict__ hbuf, const float* __restrict__ g,
                          const float* __restrict__ bb) {
    int row = blockIdx.x;
    const float* x = hbuf + (size_t)row * HEAD_DIM;
    int tid = threadIdx.x;   // 128
    float v[4]; float s = 0.f, s2 = 0.f;
    #pragma unroll
    for (int i = 0; i < 4; i++) {
        v[i] = x[tid + i * 128];
        s += v[i]; s2 += v[i] * v[i];
    }
    #pragma unroll
    for (int o = 16; o; o >>= 1) {
        s  += __shfl_down_sync(0xffffffffu, s, o);
        s2 += __shfl_down_sync(0xffffffffu, s2, o);
    }
    __shared__ float ss[4], ss2[4];
    if ((tid & 31) == 0) { ss[tid >> 5] = s; ss2[tid >> 5] = s2; }
    __syncthreads();
    s  = ss[0] + ss[1] + ss[2] + ss[3];
    s2 = ss2[0] + ss2[1] + ss2[2] + ss2[3];
    float mu  = s * (1.f / HEAD_DIM);
    float var = s2 * (1.f / HEAD_DIM) - mu * mu;
    float rs  = rsqrtf(var + 1e-5f);
    #pragma unroll
    for (int i = 0; i < 4; i++) {
        int j = tid + i * 128;
        float o = (v[i] - mu) * rs * g[j] + bb[j];
        __nv_bfloat16 hh, ll; split2(o, hh, ll);
        g_xnh[(size_t)row * HEAD_DIM + j] = hh;
        g_xnl[(size_t)row * HEAD_DIM + j] = ll;
    }
}

// ---------------- fp32 -> bf16 hi/lo split (weights) ----------------
__global__ void split_kernel(const float* __restrict__ src,
                             __nv_bfloat16* __restrict__ dh,
                             __nv_bfloat16* __restrict__ dl, int n4) {
    int stride = gridDim.x * blockDim.x;
    for (int i = blockIdx.x * blockDim.x + threadIdx.x; i < n4; i += stride) {
        float4 v = reinterpret_cast<const float4*>(src)[i];
        __nv_bfloat16 h0, l0, h1, l1, h2, l2, h3, l3;
        split2(v.x, h0, l0); split2(v.y, h1, l1);
        split2(v.z, h2, l2); split2(v.w, h3, l3);
        __nv_bfloat162* ph = reinterpret_cast<__nv_bfloat162*>(dh) + i * 2;
        __nv_bfloat162* pl = reinterpret_cast<__nv_bfloat162*>(dl) + i * 2;
        ph[0] = __nv_bfloat162{h0, h1}; ph[1] = __nv_bfloat162{h2, h3};
        pl[0] = __nv_bfloat162{l0, l1}; pl[1] = __nv_bfloat162{l2, l3};
    }
}

// ================= bf16x3 tensor-core GEMM (128x128x32, round-4 config) ======
// C[M,N] = (Ah+Al)[M,K] @ (Bh+Bl); D += Ah*Bh + Al*Bh + Ah*Bl.
// Block 128x128x32, 8 warps (2x4), warp tile 64x32, m16n8k16 bf16, 2-stage cp.async.
// TRANSB: B source is [N,K]; else [K,N]. N ragged only with TRANSB.
constexpr int BM = 128, BN = 128, BK = 32;
constexpr int ASTR = BK + 8;        // 40  ([m][k] & [n][k] tiles)
constexpr int BSTR = BN + 8;        // 136 ([k][n] tiles)
constexpr int TILE_E = 5120;        // elems per stage per array (max of layouts)
constexpr int SMEM_BYTES = 4 * 2 * TILE_E * 2;   // 4 arrays * 2 stages * bf16

template<bool TRANSB>
__device__ __forceinline__ void load_stage(
    __nv_bfloat16* sm, int stage, int k0,
    const __nv_bfloat16* Ah, const __nv_bfloat16* Al,
    const __nv_bfloat16* Bh, const __nv_bfloat16* Bl,
    int N, int K, int crow, int ccol, int tid)
{
    __nv_bfloat16* As_h = sm + stage * TILE_E;
    __nv_bfloat16* As_l = sm + 2 * TILE_E + stage * TILE_E;
    __nv_bfloat16* Bs_h = sm + 4 * TILE_E + stage * TILE_E;
    __nv_bfloat16* Bs_l = sm + 6 * TILE_E + stage * TILE_E;
    #pragma unroll
    for (int i = 0; i < 2; i++) {
        int q = tid + i * 256;
        int row = q >> 2, c8 = (q & 3) * 8;
        size_t goff = (size_t)(crow + row) * K + k0 + c8;
        uint32_t soff = row * ASTR + c8;
        cp16(smem_u32(As_h + soff), Ah + goff, true);
        cp16(smem_u32(As_l + soff), Al + goff, true);
    }
    if (!TRANSB) {
        #pragma unroll
        for (int i = 0; i < 2; i++) {
            int q = tid + i * 256;
            int row = q >> 4, c8 = (q & 15) * 8;
            size_t goff = (size_t)(k0 + row) * N + ccol + c8;
            uint32_t soff = row * BSTR + c8;
            cp16(smem_u32(Bs_h + soff), Bh + goff, true);
            cp16(smem_u32(Bs_l + soff), Bl + goff, true);
        }
    } else {
        #pragma unroll
        for (int i = 0; i < 2; i++) {
            int q = tid + i * 256;
            int row = q >> 2, c8 = (q & 3) * 8;
            bool ok = (ccol + row) < N;
            size_t goff = ok ? ((size_t)(ccol + row) * K + k0 + c8) : 0;
            uint32_t soff = row * ASTR + c8;
            cp16(smem_u32(Bs_h + soff), Bh + goff, ok);
            cp16(smem_u32(Bs_l + soff), Bl + goff, ok);
        }
    }
}

__device__ __forceinline__ void load_afrag(uint32_t a[4][4], const __nv_bfloat16* As,
                                           int warpM, int lane, int kk) {
    int lrow = warpM + (lane & 15);
    int lcol = kk + ((lane >> 4) << 3);
    #pragma unroll
    for (int mt = 0; mt < 4; mt++)
        ldm_x4(a[mt], smem_u32(As + (lrow + mt * 16) * ASTR + lcol));
}

template<bool TRANSB>
__device__ __forceinline__ void load_bfrag(uint32_t b[4][2], const __nv_bfloat16* Bs,
                                           int warpN, int lane, int kk) {
    int j = lane >> 3, r8 = lane & 7;
    if (!TRANSB) {
        int krow = kk + r8 + ((j & 1) << 3);
        #pragma unroll
        for (int np = 0; np < 2; np++) {
            int ncol = warpN + np * 16 + ((j >> 1) << 3);
            uint32_t r[4];
            ldm_x4_t(r, smem_u32(Bs + krow * BSTR + ncol));
            b[np * 2][0] = r[0]; b[np * 2][1] = r[1];
            b[np * 2 + 1][0] = r[2]; b[np * 2 + 1][1] = r[3];
        }
    } else {
        int kcol = kk + ((j & 1) << 3);
        #pragma unroll
        for (int np = 0; np < 2; np++) {
            int nrow = warpN + np * 16 + r8 + ((j >> 1) << 3);
            uint32_t r[4];
            ldm_x4(r, smem_u32(Bs + nrow * ASTR + kcol));
            b[np * 2][0] = r[0]; b[np * 2][1] = r[1];
            b[np * 2 + 1][0] = r[2]; b[np * 2 + 1][1] = r[3];
        }
    }
}

template<bool TRANSB, bool BIAS, bool GELU, bool SPLITOUT, bool RESID>
__global__ void __launch_bounds__(256, 1) gemm_bf3(
    int M, int N, int K,
    const __nv_bfloat16* __restrict__ Ah, const __nv_bfloat16* __restrict__ Al,
    const __nv_bfloat16* __restrict__ Bh, const __nv_bfloat16* __restrict__ Bl,
    const float* __restrict__ bias, float* __restrict__ C,
    __nv_bfloat16* __restrict__ Oh, __nv_bfloat16* __restrict__ Ol)
{
    extern __shared__ __nv_bfloat16 sm[];
    const int tid  = threadIdx.x;
    const int lane = tid & 31;
    const int warp = tid >> 5;
    const int crow = blockIdx.y * BM;
    const int ccol = blockIdx.x * BN;
    const int warpM = (warp >> 2) * 64;
    const int warpN = (warp & 3) * 32;
    const int r = lane >> 2, c = lane & 3;

    float acc[4][4][4];
    #pragma unroll
    for (int mt = 0; mt < 4; mt++)
        #pragma unroll
        for (int nt = 0; nt < 4; nt++)
            #pragma unroll
            for (int i = 0; i < 4; i++) acc[mt][nt][i] = 0.f;

    const int KT = K / BK;
    load_stage<TRANSB>(sm, 0, 0, Ah, Al, Bh, Bl, N, K, crow, ccol, tid);
    asm volatile("cp.async.commit_group;" ::: "memory");

    for (int kt = 0; kt < KT; kt++) {
        if (kt + 1 < KT) {
            load_stage<TRANSB>(sm, (kt + 1) & 1, (kt + 1) * BK,
                               Ah, Al, Bh, Bl, N, K, crow, ccol, tid);
            asm volatile("cp.async.commit_group;" ::: "memory");
            asm volatile("cp.async.wait_group 1;" ::: "memory");
        } else {
            asm volatile("cp.async.wait_group 0;" ::: "memory");
        }
        __syncthreads();

        const int st = kt & 1;
        const __nv_bfloat16* As_h = sm + st * TILE_E;
        const __nv_bfloat16* As_l = sm + 2 * TILE_E + st * TILE_E;
        const __nv_bfloat16* Bs_h = sm + 4 * TILE_E + st * TILE_E;
        const __nv_bfloat16* Bs_l = sm + 6 * TILE_E + st * TILE_E;

        #pragma unroll
        for (int ks = 0; ks < 2; ks++) {
            const int kk = ks * 16;
            uint32_t ah[4][4], al[4][4], bh[4][2], bl[4][2];
            load_afrag(ah, As_h, warpM, lane, kk);
            load_bfrag<TRANSB>(bh, Bs_h, warpN, lane, kk);
            #pragma unroll
            for (int mt = 0; mt < 4; mt++)
                #pragma unroll
                for (int nt = 0; nt < 4; nt++)
                    MMA_BF16(acc[mt][nt], ah[mt], bh[nt]);
            load_afrag(al, As_l, warpM, lane, kk);
            #pragma unroll
            for (int mt = 0; mt < 4; mt++)
                #pragma unroll
                for (int nt = 0; nt < 4; nt++)
                    MMA_BF16(acc[mt][nt], al[mt], bh[nt]);
            load_bfrag<TRANSB>(bl, Bs_l, warpN, lane, kk);
            #pragma unroll
            for (int mt = 0; mt < 4; mt++)
                #pragma unroll
                for (int nt = 0; nt < 4; nt++)
                    MMA_BF16(acc[mt][nt], ah[mt], bl[nt]);
        }
        __syncthreads();
    }

    // ---- epilogue ----
    #pragma unroll
    for (int mt = 0; mt < 4; mt++) {
        #pragma unroll
        for (int nt = 0; nt < 4; nt++) {
            int m0 = crow + warpM + mt * 16;
            int n0 = ccol + warpN + nt * 8;
            #pragma unroll
            for (int half = 0; half < 2; half++) {
                int m = m0 + r + half * 8;
                int n = n0 + c * 2;
                if (n >= N) continue;   // pairs never straddle (N even)
                float v0 = acc[mt][nt][half * 2 + 0];
                float v1 = acc[mt][nt][half * 2 + 1];
                if (BIAS) { v0 += bias[n]; v1 += bias[n + 1]; }
                if (GELU) { v0 = gelu_exact(v0); v1 = gelu_exact(v1); }
                if (RESID) {
                    float2 o = *reinterpret_cast<float2*>(C + (size_t)m * N + n);
                    v0 += o.x; v1 += o.y;
                }
                if (SPLITOUT) {
                    __nv_bfloat16 h0, l0, h1, l1;
                    split2(v0, h0, l0); split2(v1, h1, l1);
                    *reinterpret_cast<__nv_bfloat162*>(Oh + (size_t)m * N + n) =
                        __nv_bfloat162{h0, h1};
                    *reinterpret_cast<__nv_bfloat162*>(Ol + (size_t)m * N + n) =
                        __nv_bfloat162{l0, l1};
                } else {
                    *reinterpret_cast<float2*>(C + (size_t)m * N + n) =
                        make_float2(v0, v1);
                }
            }
        }
    }
}

// ---------------- launch ----------------
extern "C" void kernel_launch(void* const* d_in, const int* in_sizes, int n_in,
                              void* d_out, int out_size) {
    const int*   node_idx  = (const int*)  d_in[0];
    const int*   edge_idx  = (const int*)  d_in[1];
    const float* edge_w    = (const float*)d_in[2];
    const float* frozen    = (const float*)d_in[3];
    const float* W_root    = (const float*)d_in[4];
    const float* W_nbr     = (const float*)d_in[5];
    const float* b_mp      = (const float*)d_in[6];
    const float* W_post    = (const float*)d_in[7];
    const float* b_post    = (const float*)d_in[8];
    const float* fallback  = (const float*)d_in[9];
    const float* W_in      = (const float*)d_in[10];
    const float* b_in      = (const float*)d_in[11];
    const float* ln_g      = (const float*)d_in[12];
    const float* ln_b      = (const float*)d_in[13];
    const float* W1        = (const float*)d_in[14];
    const float* b1        = (const float*)d_in[15];
    const float* W2        = (const float*)d_in[16];
    const float* W_bil     = (const float*)d_in[17];
    const float* out_emb   = (const float*)d_in[18];
    float*       logits    = (float*)d_out;

    float *p_h;
    cudaGetSymbolAddress((void**)&p_h, g_h);
    __nv_bfloat16 *p_perth, *p_pertl, *p_xnh, *p_xnl, *p_acth, *p_actl;
    __nv_bfloat16 *p_hsh, *p_hsl, *p_projh, *p_projl;
    __nv_bfloat16 *p_Winh, *p_Winl, *p_W1h, *p_W1l, *p_W2h, *p_W2l;
    __nv_bfloat16 *p_bilh, *p_bill, *p_oeh, *p_oel;
    cudaGetSymbolAddress((void**)&p_perth, g_perth);
    cudaGetSymbolAddress((void**)&p_pertl, g_pertl);
    cudaGetSymbolAddress((void**)&p_xnh,  g_xnh);
    cudaGetSymbolAddress((void**)&p_xnl,  g_xnl);
    cudaGetSymbolAddress((void**)&p_acth, g_acth);
    cudaGetSymbolAddress((void**)&p_actl, g_actl);
    cudaGetSymbolAddress((void**)&p_hsh,  g_hsh);
    cudaGetSymbolAddress((void**)&p_hsl,  g_hsl);
    cudaGetSymbolAddress((void**)&p_projh, g_projh);
    cudaGetSymbolAddress((void**)&p_projl, g_projl);
    cudaGetSymbolAddress((void**)&p_Winh, g_Winh);
    cudaGetSymbolAddress((void**)&p_Winl, g_Winl);
    cudaGetSymbolAddress((void**)&p_W1h,  g_W1h);
    cudaGetSymbolAddress((void**)&p_W1l,  g_W1l);
    cudaGetSymbolAddress((void**)&p_W2h,  g_W2h);
    cudaGetSymbolAddress((void**)&p_W2l,  g_W2l);
    cudaGetSymbolAddress((void**)&p_bilh, g_bilh);
    cudaGetSymbolAddress((void**)&p_bill, g_bill);
    cudaGetSymbolAddress((void**)&p_oeh,  g_oeh);
    cudaGetSymbolAddress((void**)&p_oel,  g_oel);

    // dynamic-smem opt-in per instantiation (idempotent)
    cudaFuncSetAttribute(gemm_bf3<false, true,  true,  false, false>,
        cudaFuncAttributeMaxDynamicSharedMemorySize, SMEM_BYTES);
    cudaFuncSetAttribute(gemm_bf3<false, true,  true,  true,  false>,
        cudaFuncAttributeMaxDynamicSharedMemorySize, SMEM_BYTES);
    cudaFuncSetAttribute(gemm_bf3<false, false, false, false, true>,
        cudaFuncAttributeMaxDynamicSharedMemorySize, SMEM_BYTES);
    cudaFuncSetAttribute(gemm_bf3<false, false, false, true,  true>,
        cudaFuncAttributeMaxDynamicSharedMemorySize, SMEM_BYTES);
    cudaFuncSetAttribute(gemm_bf3<false, false, false, true,  false>,
        cudaFuncAttributeMaxDynamicSharedMemorySize, SMEM_BYTES);
    cudaFuncSetAttribute(gemm_bf3<true,  false, false, false, false>,
        cudaFuncAttributeMaxDynamicSharedMemorySize, SMEM_BYTES);

    // --- weight splits (bf16 hi/lo) ---
    split_kernel<<<256, 256>>>(W_in,   p_Winh, p_Winl, GNN_DIM * HEAD_DIM / 4);
    split_kernel<<<2048, 256>>>(W1,    p_W1h,  p_W1l,  N_RES * HEAD_DIM * FF_DIM / 4);
    split_kernel<<<2048, 256>>>(W2,    p_W2h,  p_W2l,  N_RES * FF_DIM * HEAD_DIM / 4);
    split_kernel<<<512, 256>>>(W_bil,  p_bilh, p_bill, HEAD_DIM * BIL_DIM / 4);
    split_kernel<<<1024, 256>>>(out_emb, p_oeh, p_oel, N_GENES * HEAD_DIM / 4);

    // --- graph phase (compact slots) ---
    zero_kernel<<<512, 256>>>();
    mark_kernel<<<(BATCH + 255) / 256, 256>>>(node_idx);
    {
        int warps = (N_EDGES + 31) / 32;
        int blocks = (warps + 7) / 8;
        edge_kernel<<<blocks, 256>>>(edge_idx, edge_w, frozen);
    }
    wc_kernel<<<GNN_DIM, GNN_DIM>>>(W_root, W_nbr, W_post);
    bc_kernel<<<1, GNN_DIM>>>(b_mp, W_post, b_post);
    pert_kernel<<<BATCH / 8, GNN_DIM>>>(node_idx, frozen, fallback);

    // --- dense head ---
    // h = gelu(pert @ W_in + b_in)
    {
        dim3 grid(HEAD_DIM / BN, BATCH / BM);
        gemm_bf3<false, true, true, false, false><<<grid, 256, SMEM_BYTES>>>(
            BATCH, HEAD_DIM, GNN_DIM, p_perth, p_pertl, p_Winh, p_Winl,
            b_in, p_h, nullptr, nullptr);
    }
    for (int i = 0; i < N_RES; i++) {
        ln_kernel<<<BATCH, 128>>>(p_h, ln_g + (size_t)i * HEAD_DIM,
                                  ln_b + (size_t)i * HEAD_DIM);
        dim3 g1(FF_DIM / BN, BATCH / BM);
        gemm_bf3<false, true, true, true, false><<<g1, 256, SMEM_BYTES>>>(
            BATCH, FF_DIM, HEAD_DIM, p_xnh, p_xnl,
            p_W1h + (size_t)i * HEAD_DIM * FF_DIM, p_W1l + (size_t)i * HEAD_DIM * FF_DIM,
            b1 + (size_t)i * FF_DIM, nullptr, p_acth, p_actl);
        dim3 g2(HEAD_DIM / BN, BATCH / BM);
        if (i < N_RES - 1) {
            gemm_bf3<false, false, false, false, true><<<g2, 256, SMEM_BYTES>>>(
                BATCH, HEAD_DIM, FF_DIM, p_acth, p_actl,
                p_W2h + (size_t)i * FF_DIM * HEAD_DIM, p_W2l + (size_t)i * FF_DIM * HEAD_DIM,
                nullptr, p_h, nullptr, nullptr);
        } else {
            // last block: residual-add + split h for the bil GEMM (fused; h itself
            // is not needed after this point, so only the split is written)
            gemm_bf3<false, false, false, true, true><<<g2, 256, SMEM_BYTES>>>(
                BATCH, HEAD_DIM, FF_DIM, p_acth, p_actl,
                p_W2h + (size_t)i * FF_DIM * HEAD_DIM, p_W2l + (size_t)i * FF_DIM * HEAD_DIM,
                nullptr, p_h, p_hsh, p_hsl);
        }
    }
    // proj = h @ W_bil (split output)
    {
        dim3 grid(BIL_DIM / BN, BATCH / BM);
        gemm_bf3<false, false, false, true, false><<<grid, 256, SMEM_BYTES>>>(
            BATCH, BIL_DIM, HEAD_DIM, p_hsh, p_hsl, p_bilh, p_bill,
            nullptr, nullptr, p_projh, p_projl);
    }
    // logits = reshape(proj,[B*3,512]) @ out_emb^T
    {
        dim3 grid((N_GENES + BN - 1) / BN, (BATCH * N_CLASSES) / BM);
        gemm_bf3<true, false, false, false, false><<<grid, 256, SMEM_BYTES>>>(
            BATCH * N_CLASSES, N_GENES, HEAD_DIM, p_projh, p_projl, p_oeh, p_oel,
            nullptr, logits, nullptr, nullptr);
    }
}

// round 11
// speedup vs baseline: 1.3536x; 1.1157x over previous
#include <cuda_runtime.h>
#include <cuda_bf16.h>
#include <math.h>
#include <stdint.h>

// ---------------- problem constants ----------------
#define N_NODES   19385
#define N_EDGES   1200000
#define GNN_DIM   256
#define HEAD_DIM  512
#define EXPAND    4
#define N_CLASSES 3
#define N_GENES   6640
#define N_RES     6
#define BATCH     2048
#define FF_DIM    (HEAD_DIM * EXPAND)    // 2048
#define BIL_DIM   (N_CLASSES * HEAD_DIM) // 1536

// ---------------- fp32 scratch ----------------
__device__ float g_aggrc[(size_t)BATCH * GNN_DIM];   // compact aggregation (2 MB)
__device__ int   g_slot[N_NODES];                    // node -> compact slot (-1 = unused)
__device__ float g_Wc1[GNN_DIM * GNN_DIM];
__device__ float g_Wc2[GNN_DIM * GNN_DIM];
__device__ float g_bc[GNN_DIM];
__device__ float g_h[(size_t)BATCH * HEAD_DIM];

// ---------------- bf16 split scratch (hi/lo pairs) ----------------
__device__ __nv_bfloat16 g_perth[(size_t)BATCH * GNN_DIM];
__device__ __nv_bfloat16 g_pertl[(size_t)BATCH * GNN_DIM];
__device__ __nv_bfloat16 g_xnh[(size_t)BATCH * HEAD_DIM];
__device__ __nv_bfloat16 g_xnl[(size_t)BATCH * HEAD_DIM];
__device__ __nv_bfloat16 g_acth[(size_t)BATCH * FF_DIM];
__device__ __nv_bfloat16 g_actl[(size_t)BATCH * FF_DIM];
__device__ __nv_bfloat16 g_hsh[(size_t)BATCH * HEAD_DIM];
__device__ __nv_bfloat16 g_hsl[(size_t)BATCH * HEAD_DIM];
__device__ __nv_bfloat16 g_projh[(size_t)BATCH * BIL_DIM];
__device__ __nv_bfloat16 g_projl[(size_t)BATCH * BIL_DIM];
// weight splits ([K,N] layout)
__device__ __nv_bfloat16 g_Winh[GNN_DIM * HEAD_DIM];
__device__ __nv_bfloat16 g_Winl[GNN_DIM * HEAD_DIM];
__device__ __nv_bfloat16 g_W1h[(size_t)N_RES * HEAD_DIM * FF_DIM];
__device__ __nv_bfloat16 g_W1l[(size_t)N_RES * HEAD_DIM * FF_DIM];
__device__ __nv_bfloat16 g_W2h[(size_t)N_RES * FF_DIM * HEAD_DIM];
__device__ __nv_bfloat16 g_W2l[(size_t)N_RES * FF_DIM * HEAD_DIM];
__device__ __nv_bfloat16 g_bilh[HEAD_DIM * BIL_DIM];
__device__ __nv_bfloat16 g_bill[HEAD_DIM * BIL_DIM];
__device__ __nv_bfloat16 g_oeh[(size_t)N_GENES * HEAD_DIM];
__device__ __nv_bfloat16 g_oel[(size_t)N_GENES * HEAD_DIM];

// ---------------- helpers ----------------
__device__ __forceinline__ float gelu_exact(float v) {
    return 0.5f * v * (1.0f + erff(v * 0.70710678118654752f));
}
__device__ __forceinline__ void split2(float x, __nv_bfloat16& h, __nv_bfloat16& l) {
    h = __float2bfloat16_rn(x);
    l = __float2bfloat16_rn(x - __bfloat162float(h));
}
__device__ __forceinline__ uint32_t smem_u32(const void* p) {
    return (uint32_t)__cvta_generic_to_shared(p);
}
__device__ __forceinline__ void cp16(uint32_t dst, const void* src, bool pred) {
    int sz = pred ? 16 : 0;
    asm volatile("cp.async.cg.shared.global [%0], [%1], 16, %2;\n"
                 :: "r"(dst), "l"(src), "r"(sz));
}
__device__ __forceinline__ void ldm_x4(uint32_t* r, uint32_t addr) {
    asm volatile("ldmatrix.sync.aligned.m8n8.x4.shared.b16 {%0,%1,%2,%3}, [%4];"
                 : "=r"(r[0]), "=r"(r[1]), "=r"(r[2]), "=r"(r[3]) : "r"(addr));
}
__device__ __forceinline__ void ldm_x4_t(uint32_t* r, uint32_t addr) {
    asm volatile("ldmatrix.sync.aligned.m8n8.x4.trans.shared.b16 {%0,%1,%2,%3}, [%4];"
                 : "=r"(r[0]), "=r"(r[1]), "=r"(r[2]), "=r"(r[3]) : "r"(addr));
}
#define MMA_BF16(D, A, B)                                                   \
    asm volatile(                                                           \
        "mma.sync.aligned.m16n8k16.row.col.f32.bf16.bf16.f32 "              \
        "{%0,%1,%2,%3},{%4,%5,%6,%7},{%8,%9},{%0,%1,%2,%3};"                \
        : "+f"((D)[0]), "+f"((D)[1]), "+f"((D)[2]), "+f"((D)[3])            \
        : "r"((A)[0]), "r"((A)[1]), "r"((A)[2]), "r"((A)[3]),               \
          "r"((B)[0]), "r"((B)[1]))

// ---------------- zero compact scratch + slot init ----------------
__global__ void zero_kernel() {
    int stride = gridDim.x * blockDim.x;
    int tid = blockIdx.x * blockDim.x + threadIdx.x;
    int total4 = BATCH * (GNN_DIM / 4);
    float4* a4 = reinterpret_cast<float4*>(g_aggrc);
    for (int i = tid; i < total4; i += stride)
        a4[i] = make_float4(0.f, 0.f, 0.f, 0.f);
    for (int i = tid; i < N_NODES; i += stride)
        g_slot[i] = -1;
}

// ---------------- claim compact slots for needed nodes ----------------
__global__ void mark_kernel(const int* __restrict__ idx) {
    int b = blockIdx.x * blockDim.x + threadIdx.x;
    if (b < BATCH) {
        int n = idx[b];
        if (n >= 0) atomicCAS(&g_slot[n], -1, b);
    }
}

// ---------------- filtered edge scatter-add into compact buffer ----------------
__global__ void edge_kernel(const int* __restrict__ ei, const float* __restrict__ ew,
                            const float* __restrict__ x0) {
    const int lane = threadIdx.x & 31;
    const int warp = (blockIdx.x * blockDim.x + threadIdx.x) >> 5;
    const int e0 = warp * 32;
    if (e0 >= N_EDGES) return;
    const int e = e0 + lane;
    int sl = -1, s = 0; float w = 0.f;
    if (e < N_EDGES) {
        int d = ei[N_EDGES + e];
        sl = g_slot[d];
        if (sl >= 0) { s = ei[e]; w = ew[e]; }
    }
    unsigned mask = __ballot_sync(0xffffffffu, sl >= 0);
    while (mask) {
        int b = __ffs(mask) - 1; mask &= (mask - 1);
        int   ss = __shfl_sync(0xffffffffu, s, b);
        int   dd = __shfl_sync(0xffffffffu, sl, b);
        float ww = __shfl_sync(0xffffffffu, w, b);
        const float4* xr = reinterpret_cast<const float4*>(x0 + (size_t)ss * GNN_DIM);
        float* ar = g_aggrc + (size_t)dd * GNN_DIM;
        #pragma unroll
        for (int i = 0; i < 2; i++) {
            int c = lane + i * 32;
            float4 v = xr[c];
            asm volatile("red.global.add.v4.f32 [%0], {%1,%2,%3,%4};"
                         :: "l"(ar + c * 4), "f"(v.x * ww), "f"(v.y * ww),
                            "f"(v.z * ww), "f"(v.w * ww) : "memory");
        }
    }
}

// ---------------- fused: fold weights + bc + W_in split ----------------
// grid = 385 blocks x 256 threads:
//   [0,256)   : Wc1/Wc2 row i = blockIdx.x
//   256       : bc
//   (256,385] : W_in fp32 -> bf16 hi/lo split (128 blocks x 256 thr x 1 float4)
__global__ void fused_wc_kernel(const float* __restrict__ Wr, const float* __restrict__ Wn,
                                const float* __restrict__ Wp,
                                const float* __restrict__ bmp, const float* __restrict__ bpost,
                                const float* __restrict__ Win) {
    int bx = blockIdx.x, j = threadIdx.x;
    if (bx < GNN_DIM) {
        __shared__ float r[GNN_DIM], nn[GNN_DIM];
        r[j]  = Wr[bx * GNN_DIM + j] + (bx == j ? 1.f : 0.f);
        nn[j] = Wn[bx * GNN_DIM + j];
        __syncthreads();
        float a1 = 0.f, a2 = 0.f;
        #pragma unroll 4
        for (int k = 0; k < GNN_DIM; k++) {
            float wp = Wp[k * GNN_DIM + j];
            a1 += r[k] * wp; a2 += nn[k] * wp;
        }
        g_Wc1[bx * GNN_DIM + j] = a1;
        g_Wc2[bx * GNN_DIM + j] = a2;
    } else if (bx == GNN_DIM) {
        float a = bpost[j];
        #pragma unroll 4
        for (int k = 0; k < GNN_DIM; k++)
            a += bmp[k] * Wp[k * GNN_DIM + j];
        g_bc[j] = a;
    } else {
        int i = (bx - GNN_DIM - 1) * 256 + j;   // float4 index, 32768 total
        float4 v = reinterpret_cast<const float4*>(Win)[i];
        __nv_bfloat16 h0, l0, h1, l1, h2, l2, h3, l3;
        split2(v.x, h0, l0); split2(v.y, h1, l1);
        split2(v.z, h2, l2); split2(v.w, h3, l3);
        __nv_bfloat162* ph = reinterpret_cast<__nv_bfloat162*>(g_Winh) + i * 2;
        __nv_bfloat162* pl = reinterpret_cast<__nv_bfloat162*>(g_Winl) + i * 2;
        ph[0] = __nv_bfloat162{h0, h1}; ph[1] = __nv_bfloat162{h2, h3};
        pl[0] = __nv_bfloat162{l0, l1}; pl[1] = __nv_bfloat162{l2, l3};
    }
}

// ---------------- per-batch-row node transform -> split pert ----------------
__global__ void pert_kernel(const int* __restrict__ idx, const float* __restrict__ x0,
                            const float* __restrict__ fb) {
    constexpr int RPB = 8;
    __shared__ float xr[RPB][GNN_DIM];
    __shared__ float ar[RPB][GNN_DIM];
    __shared__ int   ns[RPB], sl[RPB];
    int j = threadIdx.x;
    int b0 = blockIdx.x * RPB;
    if (j < RPB) {
        int n = idx[b0 + j];
        ns[j] = n;
        sl[j] = (n >= 0) ? g_slot[n] : 0;
    }
    __syncthreads();
    #pragma unroll
    for (int r = 0; r < RPB; r++) {
        int n = ns[r]; int sn = (n < 0) ? 0 : n;
        xr[r][j] = x0[(size_t)sn * GNN_DIM + j];
        ar[r][j] = g_aggrc[(size_t)sl[r] * GNN_DIM + j];
    }
    __syncthreads();
    float acc[RPB];
    #pragma unroll
    for (int r = 0; r < RPB; r++) acc[r] = g_bc[j];
    for (int k = 0; k < GNN_DIM; k++) {
        float w1 = g_Wc1[k * GNN_DIM + j];
        float w2 = g_Wc2[k * GNN_DIM + j];
        #pragma unroll
        for (int r = 0; r < RPB; r++)
            acc[r] += xr[r][k] * w1 + ar[r][k] * w2;
    }
    float fbj = fb[j];
    #pragma unroll
    for (int r = 0; r < RPB; r++) {
        float v = (ns[r] >= 0) ? acc[r] : fbj;
        __nv_bfloat16 h, l; split2(v, h, l);
        g_perth[(size_t)(b0 + r) * GNN_DIM + j] = h;
        g_pertl[(size_t)(b0 + r) * GNN_DIM + j] = l;
    }
}

// ---------------- layernorm -> split xn ----------------
__global__ void ln_kernel(const float* __restrict__ hbuf, const float* __restrict__ g,
                          const float* __restrict__ bb) {
    int row = blockIdx.x;
    const float* x = hbuf + (size_t)row * HEAD_DIM;
    int tid = threadIdx.x;   // 128
    float v[4]; float s = 0.f, s2 = 0.f;
    #pragma unroll
    for (int i = 0; i < 4; i++) {
        v[i] = x[tid + i * 128];
        s += v[i]; s2 += v[i] * v[i];
    }
    #pragma unroll
    for (int o = 16; o; o >>= 1) {
        s  += __shfl_down_sync(0xffffffffu, s, o);
        s2 += __shfl_down_sync(0xffffffffu, s2, o);
    }
    __shared__ float ss[4], ss2[4];
    if ((tid & 31) == 0) { ss[tid >> 5] = s; ss2[tid >> 5] = s2; }
    __syncthreads();
    s  = ss[0] + ss[1] + ss[2] + ss[3];
    s2 = ss2[0] + ss2[1] + ss2[2] + ss2[3];
    float mu  = s * (1.f / HEAD_DIM);
    float var = s2 * (1.f / HEAD_DIM) - mu * mu;
    float rs  = rsqrtf(var + 1e-5f);
    #pragma unroll
    for (int i = 0; i < 4; i++) {
        int j = tid + i * 128;
        float o = (v[i] - mu) * rs * g[j] + bb[j];
        __nv_bfloat16 hh, ll; split2(o, hh, ll);
        g_xnh[(size_t)row * HEAD_DIM + j] = hh;
        g_xnl[(size_t)row * HEAD_DIM + j] = ll;
    }
}

// ---------------- fp32 -> bf16 hi/lo split (weights) ----------------
__global__ void split_kernel(const float* __restrict__ src,
                             __nv_bfloat16* __restrict__ dh,
                             __nv_bfloat16* __restrict__ dl, int n4) {
    int stride = gridDim.x * blockDim.x;
    for (int i = blockIdx.x * blockDim.x + threadIdx.x; i < n4; i += stride) {
        float4 v = reinterpret_cast<const float4*>(src)[i];
        __nv_bfloat16 h0, l0, h1, l1, h2, l2, h3, l3;
        split2(v.x, h0, l0); split2(v.y, h1, l1);
        split2(v.z, h2, l2); split2(v.w, h3, l3);
        __nv_bfloat162* ph = reinterpret_cast<__nv_bfloat162*>(dh) + i * 2;
        __nv_bfloat162* pl = reinterpret_cast<__nv_bfloat162*>(dl) + i * 2;
        ph[0] = __nv_bfloat162{h0, h1}; ph[1] = __nv_bfloat162{h2, h3};
        pl[0] = __nv_bfloat162{l0, l1}; pl[1] = __nv_bfloat162{l2, l3};
    }
}

// ================= bf16x3 tensor-core GEMM (128x128x32, occupancy 2) =========
constexpr int BM = 128, BN = 128, BK = 32;
constexpr int ASTR = BK + 8;        // 40
constexpr int BSTR = BN + 8;        // 136
constexpr int TILE_E = 5120;
constexpr int SMEM_BYTES = 4 * 2 * TILE_E * 2;   // 81920 B -> 2 CTAs/SM fits

template<bool TRANSB>
__device__ __forceinline__ void load_stage(
    __nv_bfloat16* sm, int stage, int k0,
    const __nv_bfloat16* Ah, const __nv_bfloat16* Al,
    const __nv_bfloat16* Bh, const __nv_bfloat16* Bl,
    int N, int K, int crow, int ccol, int tid)
{
    __nv_bfloat16* As_h = sm + stage * TILE_E;
    __nv_bfloat16* As_l = sm + 2 * TILE_E + stage * TILE_E;
    __nv_bfloat16* Bs_h = sm + 4 * TILE_E + stage * TILE_E;
    __nv_bfloat16* Bs_l = sm + 6 * TILE_E + stage * TILE_E;
    #pragma unroll
    for (int i = 0; i < 2; i++) {
        int q = tid + i * 256;
        int row = q >> 2, c8 = (q & 3) * 8;
        size_t goff = (size_t)(crow + row) * K + k0 + c8;
        uint32_t soff = row * ASTR + c8;
        cp16(smem_u32(As_h + soff), Ah + goff, true);
        cp16(smem_u32(As_l + soff), Al + goff, true);
    }
    if (!TRANSB) {
        #pragma unroll
        for (int i = 0; i < 2; i++) {
            int q = tid + i * 256;
            int row = q >> 4, c8 = (q & 15) * 8;
            size_t goff = (size_t)(k0 + row) * N + ccol + c8;
            uint32_t soff = row * BSTR + c8;
            cp16(smem_u32(Bs_h + soff), Bh + goff, true);
            cp16(smem_u32(Bs_l + soff), Bl + goff, true);
        }
    } else {
        #pragma unroll
        for (int i = 0; i < 2; i++) {
            int q = tid + i * 256;
            int row = q >> 2, c8 = (q & 3) * 8;
            bool ok = (ccol + row) < N;
            size_t goff = ok ? ((size_t)(ccol + row) * K + k0 + c8) : 0;
            uint32_t soff = row * ASTR + c8;
            cp16(smem_u32(Bs_h + soff), Bh + goff, ok);
            cp16(smem_u32(Bs_l + soff), Bl + goff, ok);
        }
    }
}

__device__ __forceinline__ void load_afrag(uint32_t a[4][4], const __nv_bfloat16* As,
                                           int warpM, int lane, int kk) {
    int lrow = warpM + (lane & 15);
    int lcol = kk + ((lane >> 4) << 3);
    #pragma unroll
    for (int mt = 0; mt < 4; mt++)
        ldm_x4(a[mt], smem_u32(As + (lrow + mt * 16) * ASTR + lcol));
}

template<bool TRANSB>
__device__ __forceinline__ void load_bfrag(uint32_t b[4][2], const __nv_bfloat16* Bs,
                                           int warpN, int lane, int kk) {
    int j = lane >> 3, r8 = lane & 7;
    if (!TRANSB) {
        int krow = kk + r8 + ((j & 1) << 3);
        #pragma unroll
        for (int np = 0; np < 2; np++) {
            int ncol = warpN + np * 16 + ((j >> 1) << 3);
            uint32_t r[4];
            ldm_x4_t(r, smem_u32(Bs + krow * BSTR + ncol));
            b[np * 2][0] = r[0]; b[np * 2][1] = r[1];
            b[np * 2 + 1][0] = r[2]; b[np * 2 + 1][1] = r[3];
        }
    } else {
        int kcol = kk + ((j & 1) << 3);
        #pragma unroll
        for (int np = 0; np < 2; np++) {
            int nrow = warpN + np * 16 + r8 + ((j >> 1) << 3);
            uint32_t r[4];
            ldm_x4(r, smem_u32(Bs + nrow * ASTR + kcol));
            b[np * 2][0] = r[0]; b[np * 2][1] = r[1];
            b[np * 2 + 1][0] = r[2]; b[np * 2 + 1][1] = r[3];
        }
    }
}

template<bool TRANSB, bool BIAS, bool GELU, bool SPLITOUT, bool RESID>
__global__ void __launch_bounds__(256, 2) gemm_bf3(
    int M, int N, int K,
    const __nv_bfloat16* __restrict__ Ah, const __nv_bfloat16* __restrict__ Al,
    const __nv_bfloat16* __restrict__ Bh, const __nv_bfloat16* __restrict__ Bl,
    const float* __restrict__ bias, float* __restrict__ C,
    __nv_bfloat16* __restrict__ Oh, __nv_bfloat16* __restrict__ Ol)
{
    extern __shared__ __nv_bfloat16 sm[];
    const int tid  = threadIdx.x;
    const int lane = tid & 31;
    const int warp = tid >> 5;
    const int crow = blockIdx.y * BM;
    const int ccol = blockIdx.x * BN;
    const int warpM = (warp >> 2) * 64;
    const int warpN = (warp & 3) * 32;
    const int r = lane >> 2, c = lane & 3;

    float acc[4][4][4];
    #pragma unroll
    for (int mt = 0; mt < 4; mt++)
        #pragma unroll
        for (int nt = 0; nt < 4; nt++)
            #pragma unroll
            for (int i = 0; i < 4; i++) acc[mt][nt][i] = 0.f;

    const int KT = K / BK;
    load_stage<TRANSB>(sm, 0, 0, Ah, Al, Bh, Bl, N, K, crow, ccol, tid);
    asm volatile("cp.async.commit_group;" ::: "memory");

    for (int kt = 0; kt < KT; kt++) {
        if (kt + 1 < KT) {
            load_stage<TRANSB>(sm, (kt + 1) & 1, (kt + 1) * BK,
                               Ah, Al, Bh, Bl, N, K, crow, ccol, tid);
            asm volatile("cp.async.commit_group;" ::: "memory");
            asm volatile("cp.async.wait_group 1;" ::: "memory");
        } else {
            asm volatile("cp.async.wait_group 0;" ::: "memory");
        }
        __syncthreads();

        const int st = kt & 1;
        const __nv_bfloat16* As_h = sm + st * TILE_E;
        const __nv_bfloat16* As_l = sm + 2 * TILE_E + st * TILE_E;
        const __nv_bfloat16* Bs_h = sm + 4 * TILE_E + st * TILE_E;
        const __nv_bfloat16* Bs_l = sm + 6 * TILE_E + st * TILE_E;

        #pragma unroll
        for (int ks = 0; ks < 2; ks++) {
            const int kk = ks * 16;
            uint32_t ah[4][4], al[4][4], bh[4][2], bl[4][2];
            load_afrag(ah, As_h, warpM, lane, kk);
            load_bfrag<TRANSB>(bh, Bs_h, warpN, lane, kk);
            #pragma unroll
            for (int mt = 0; mt < 4; mt++)
                #pragma unroll
                for (int nt = 0; nt < 4; nt++)
                    MMA_BF16(acc[mt][nt], ah[mt], bh[nt]);
            load_afrag(al, As_l, warpM, lane, kk);
            #pragma unroll
            for (int mt = 0; mt < 4; mt++)
                #pragma unroll
                for (int nt = 0; nt < 4; nt++)
                    MMA_BF16(acc[mt][nt], al[mt], bh[nt]);
            load_bfrag<TRANSB>(bl, Bs_l, warpN, lane, kk);
            #pragma unroll
            for (int mt = 0; mt < 4; mt++)
                #pragma unroll
                for (int nt = 0; nt < 4; nt++)
                    MMA_BF16(acc[mt][nt], ah[mt], bl[nt]);
        }
        __syncthreads();
    }

    // ---- epilogue ----
    #pragma unroll
    for (int mt = 0; mt < 4; mt++) {
        #pragma unroll
        for (int nt = 0; nt < 4; nt++) {
            int m0 = crow + warpM + mt * 16;
            int n0 = ccol + warpN + nt * 8;
            #pragma unroll
            for (int half = 0; half < 2; half++) {
                int m = m0 + r + half * 8;
                int n = n0 + c * 2;
                if (n >= N) continue;
                float v0 = acc[mt][nt][half * 2 + 0];
                float v1 = acc[mt][nt][half * 2 + 1];
                if (BIAS) { v0 += bias[n]; v1 += bias[n + 1]; }
                if (GELU) { v0 = gelu_exact(v0); v1 = gelu_exact(v1); }
                if (RESID) {
                    float2 o = *reinterpret_cast<float2*>(C + (size_t)m * N + n);
                    v0 += o.x; v1 += o.y;
                }
                if (SPLITOUT) {
                    __nv_bfloat16 h0, l0, h1, l1;
                    split2(v0, h0, l0); split2(v1, h1, l1);
                    *reinterpret_cast<__nv_bfloat162*>(Oh + (size_t)m * N + n) =
                        __nv_bfloat162{h0, h1};
                    *reinterpret_cast<__nv_bfloat162*>(Ol + (size_t)m * N + n) =
                        __nv_bfloat162{l0, l1};
                } else {
                    *reinterpret_cast<float2*>(C + (size_t)m * N + n) =
                        make_float2(v0, v1);
                }
            }
        }
    }
}

// ---------------- launch ----------------
extern "C" void kernel_launch(void* const* d_in, const int* in_sizes, int n_in,
                              void* d_out, int out_size) {
    const int*   node_idx  = (const int*)  d_in[0];
    const int*   edge_idx  = (const int*)  d_in[1];
    const float* edge_w    = (const float*)d_in[2];
    const float* frozen    = (const float*)d_in[3];
    const float* W_root    = (const float*)d_in[4];
    const float* W_nbr     = (const float*)d_in[5];
    const float* b_mp      = (const float*)d_in[6];
    const float* W_post    = (const float*)d_in[7];
    const float* b_post    = (const float*)d_in[8];
    const float* fallback  = (const float*)d_in[9];
    const float* W_in      = (const float*)d_in[10];
    const float* b_in      = (const float*)d_in[11];
    const float* ln_g      = (const float*)d_in[12];
    const float* ln_b      = (const float*)d_in[13];
    const float* W1        = (const float*)d_in[14];
    const float* b1        = (const float*)d_in[15];
    const float* W2        = (const float*)d_in[16];
    const float* W_bil     = (const float*)d_in[17];
    const float* out_emb   = (const float*)d_in[18];
    float*       logits    = (float*)d_out;

    float *p_h;
    cudaGetSymbolAddress((void**)&p_h, g_h);
    __nv_bfloat16 *p_perth, *p_pertl, *p_xnh, *p_xnl, *p_acth, *p_actl;
    __nv_bfloat16 *p_hsh, *p_hsl, *p_projh, *p_projl;
    __nv_bfloat16 *p_Winh, *p_Winl, *p_W1h, *p_W1l, *p_W2h, *p_W2l;
    __nv_bfloat16 *p_bilh, *p_bill, *p_oeh, *p_oel;
    cudaGetSymbolAddress((void**)&p_perth, g_perth);
    cudaGetSymbolAddress((void**)&p_pertl, g_pertl);
    cudaGetSymbolAddress((void**)&p_xnh,  g_xnh);
    cudaGetSymbolAddress((void**)&p_xnl,  g_xnl);
    cudaGetSymbolAddress((void**)&p_acth, g_acth);
    cudaGetSymbolAddress((void**)&p_actl, g_actl);
    cudaGetSymbolAddress((void**)&p_hsh,  g_hsh);
    cudaGetSymbolAddress((void**)&p_hsl,  g_hsl);
    cudaGetSymbolAddress((void**)&p_projh, g_projh);
    cudaGetSymbolAddress((void**)&p_projl, g_projl);
    cudaGetSymbolAddress((void**)&p_Winh, g_Winh);
    cudaGetSymbolAddress((void**)&p_Winl, g_Winl);
    cudaGetSymbolAddress((void**)&p_W1h,  g_W1h);
    cudaGetSymbolAddress((void**)&p_W1l,  g_W1l);
    cudaGetSymbolAddress((void**)&p_W2h,  g_W2h);
    cudaGetSymbolAddress((void**)&p_W2l,  g_W2l);
    cudaGetSymbolAddress((void**)&p_bilh, g_bilh);
    cudaGetSymbolAddress((void**)&p_bill, g_bill);
    cudaGetSymbolAddress((void**)&p_oeh,  g_oeh);
    cudaGetSymbolAddress((void**)&p_oel,  g_oel);

    cudaFuncSetAttribute(gemm_bf3<false, true,  true,  false, false>,
        cudaFuncAttributeMaxDynamicSharedMemorySize, SMEM_BYTES);
    cudaFuncSetAttribute(gemm_bf3<false, true,  true,  true,  false>,
        cudaFuncAttributeMaxDynamicSharedMemorySize, SMEM_BYTES);
    cudaFuncSetAttribute(gemm_bf3<false, false, false, false, true>,
        cudaFuncAttributeMaxDynamicSharedMemorySize, SMEM_BYTES);
    cudaFuncSetAttribute(gemm_bf3<false, false, false, true,  true>,
        cudaFuncAttributeMaxDynamicSharedMemorySize, SMEM_BYTES);
    cudaFuncSetAttribute(gemm_bf3<false, false, false, true,  false>,
        cudaFuncAttributeMaxDynamicSharedMemorySize, SMEM_BYTES);
    cudaFuncSetAttribute(gemm_bf3<true,  false, false, false, false>,
        cudaFuncAttributeMaxDynamicSharedMemorySize, SMEM_BYTES);

    // --- graph phase first so launch #5 is gemm_bf3 (ncu -s 5 -c 1) ---
    zero_kernel<<<512, 256>>>();                               // 0
    mark_kernel<<<(BATCH + 255) / 256, 256>>>(node_idx);       // 1
    {
        int warps = (N_EDGES + 31) / 32;
        int blocks = (warps + 7) / 8;
        edge_kernel<<<blocks, 256>>>(edge_idx, edge_w, frozen);  // 2
    }
    fused_wc_kernel<<<GNN_DIM + 1 + 128, GNN_DIM>>>(           // 3 (wc + bc + W_in split)
        W_root, W_nbr, W_post, b_mp, b_post, W_in);
    pert_kernel<<<BATCH / 8, GNN_DIM>>>(node_idx, frozen, fallback);  // 4

    // h = gelu(pert @ W_in + b_in)                            // 5  <-- profiled
    {
        dim3 grid(HEAD_DIM / BN, BATCH / BM);
        gemm_bf3<false, true, true, false, false><<<grid, 256, SMEM_BYTES>>>(
            BATCH, HEAD_DIM, GNN_DIM, p_perth, p_pertl, p_Winh, p_Winl,
            b_in, p_h, nullptr, nullptr);
    }

    // remaining weight splits (before their consumers)
    split_kernel<<<2048, 256>>>(W1,    p_W1h,  p_W1l,  N_RES * HEAD_DIM * FF_DIM / 4);
    split_kernel<<<2048, 256>>>(W2,    p_W2h,  p_W2l,  N_RES * FF_DIM * HEAD_DIM / 4);
    split_kernel<<<512, 256>>>(W_bil,  p_bilh, p_bill, HEAD_DIM * BIL_DIM / 4);
    split_kernel<<<1024, 256>>>(out_emb, p_oeh, p_oel, N_GENES * HEAD_DIM / 4);

    for (int i = 0; i < N_RES; i++) {
        ln_kernel<<<BATCH, 128>>>(p_h, ln_g + (size_t)i * HEAD_DIM,
                                  ln_b + (size_t)i * HEAD_DIM);
        dim3 g1(FF_DIM / BN, BATCH / BM);
        gemm_bf3<false, true, true, true, false><<<g1, 256, SMEM_BYTES>>>(
            BATCH, FF_DIM, HEAD_DIM, p_xnh, p_xnl,
            p_W1h + (size_t)i * HEAD_DIM * FF_DIM, p_W1l + (size_t)i * HEAD_DIM * FF_DIM,
            b1 + (size_t)i * FF_DIM, nullptr, p_acth, p_actl);
        dim3 g2(HEAD_DIM / BN, BATCH / BM);
        if (i < N_RES - 1) {
            gemm_bf3<false, false, false, false, true><<<g2, 256, SMEM_BYTES>>>(
                BATCH, HEAD_DIM, FF_DIM, p_acth, p_actl,
                p_W2h + (size_t)i * FF_DIM * HEAD_DIM, p_W2l + (size_t)i * FF_DIM * HEAD_DIM,
                nullptr, p_h, nullptr, nullptr);
        } else {
            gemm_bf3<false, false, false, true, true><<<g2, 256, SMEM_BYTES>>>(
                BATCH, HEAD_DIM, FF_DIM, p_acth, p_actl,
                p_W2h + (size_t)i * FF_DIM * HEAD_DIM, p_W2l + (size_t)i * FF_DIM * HEAD_DIM,
                nullptr, p_h, p_hsh, p_hsl);
        }
    }
    // proj = h @ W_bil (split output)
    {
        dim3 grid(BIL_DIM / BN, BATCH / BM);
        gemm_bf3<false, false, false, true, false><<<grid, 256, SMEM_BYTES>>>(
            BATCH, BIL_DIM, HEAD_DIM, p_hsh, p_hsl, p_bilh, p_bill,
            nullptr, nullptr, p_projh, p_projl);
    }
    // logits = reshape(proj,[B*3,512]) @ out_emb^T
    {
        dim3 grid((N_GENES + BN - 1) / BN, (BATCH * N_CLASSES) / BM);
        gemm_bf3<true, false, false, false, false><<<grid, 256, SMEM_BYTES>>>(
            BATCH * N_CLASSES, N_GENES, HEAD_DIM, p_projh, p_projl, p_oeh, p_oel,
            nullptr, logits, nullptr, nullptr);
    }
}

// round 12
// speedup vs baseline: 1.3861x; 1.0240x over previous
#include <cuda_runtime.h>
#include <cuda_bf16.h>
#include <math.h>
#include <stdint.h>

// ---------------- problem constants ----------------
#define N_NODES   19385
#define N_EDGES   1200000
#define GNN_DIM   256
#define HEAD_DIM  512
#define EXPAND    4
#define N_CLASSES 3
#define N_GENES   6640
#define N_RES     6
#define BATCH     2048
#define FF_DIM    (HEAD_DIM * EXPAND)    // 2048
#define BIL_DIM   (N_CLASSES * HEAD_DIM) // 1536

// ---------------- fp32 scratch ----------------
__device__ float g_aggrc[(size_t)BATCH * GNN_DIM];
__device__ int   g_slot[N_NODES];
__device__ float g_Wc1[GNN_DIM * GNN_DIM];
__device__ float g_Wc2[GNN_DIM * GNN_DIM];
__device__ float g_bc[GNN_DIM];
__device__ float g_h[(size_t)BATCH * HEAD_DIM];

// ---------------- bf16 split scratch (hi/lo pairs) ----------------
__device__ __nv_bfloat16 g_perth[(size_t)BATCH * GNN_DIM];
__device__ __nv_bfloat16 g_pertl[(size_t)BATCH * GNN_DIM];
__device__ __nv_bfloat16 g_xnh[(size_t)BATCH * HEAD_DIM];
__device__ __nv_bfloat16 g_xnl[(size_t)BATCH * HEAD_DIM];
__device__ __nv_bfloat16 g_acth[(size_t)BATCH * FF_DIM];
__device__ __nv_bfloat16 g_actl[(size_t)BATCH * FF_DIM];
__device__ __nv_bfloat16 g_hsh[(size_t)BATCH * HEAD_DIM];
__device__ __nv_bfloat16 g_hsl[(size_t)BATCH * HEAD_DIM];
__device__ __nv_bfloat16 g_projh[(size_t)BATCH * BIL_DIM];
__device__ __nv_bfloat16 g_projl[(size_t)BATCH * BIL_DIM];
// weight splits ([K,N] layout)
__device__ __nv_bfloat16 g_Winh[GNN_DIM * HEAD_DIM];
__device__ __nv_bfloat16 g_Winl[GNN_DIM * HEAD_DIM];
__device__ __nv_bfloat16 g_W1h[(size_t)N_RES * HEAD_DIM * FF_DIM];
__device__ __nv_bfloat16 g_W1l[(size_t)N_RES * HEAD_DIM * FF_DIM];
__device__ __nv_bfloat16 g_W2h[(size_t)N_RES * FF_DIM * HEAD_DIM];
__device__ __nv_bfloat16 g_W2l[(size_t)N_RES * FF_DIM * HEAD_DIM];
__device__ __nv_bfloat16 g_bilh[HEAD_DIM * BIL_DIM];
__device__ __nv_bfloat16 g_bill[HEAD_DIM * BIL_DIM];
__device__ __nv_bfloat16 g_oeh[(size_t)N_GENES * HEAD_DIM];
__device__ __nv_bfloat16 g_oel[(size_t)N_GENES * HEAD_DIM];

// ---------------- helpers ----------------
__device__ __forceinline__ float gelu_exact(float v) {
    return 0.5f * v * (1.0f + erff(v * 0.70710678118654752f));
}
__device__ __forceinline__ void split2(float x, __nv_bfloat16& h, __nv_bfloat16& l) {
    h = __float2bfloat16_rn(x);
    l = __float2bfloat16_rn(x - __bfloat162float(h));
}
__device__ __forceinline__ uint32_t smem_u32(const void* p) {
    return (uint32_t)__cvta_generic_to_shared(p);
}
__device__ __forceinline__ void cp16(uint32_t dst, const void* src, bool pred) {
    int sz = pred ? 16 : 0;
    asm volatile("cp.async.cg.shared.global [%0], [%1], 16, %2;\n"
                 :: "r"(dst), "l"(src), "r"(sz));
}
__device__ __forceinline__ void ldm_x4(uint32_t* r, uint32_t addr) {
    asm volatile("ldmatrix.sync.aligned.m8n8.x4.shared.b16 {%0,%1,%2,%3}, [%4];"
                 : "=r"(r[0]), "=r"(r[1]), "=r"(r[2]), "=r"(r[3]) : "r"(addr));
}
__device__ __forceinline__ void ldm_x4_t(uint32_t* r, uint32_t addr) {
    asm volatile("ldmatrix.sync.aligned.m8n8.x4.trans.shared.b16 {%0,%1,%2,%3}, [%4];"
                 : "=r"(r[0]), "=r"(r[1]), "=r"(r[2]), "=r"(r[3]) : "r"(addr));
}
#define MMA_BF16(D, A, B)                                                   \
    asm volatile(                                                           \
        "mma.sync.aligned.m16n8k16.row.col.f32.bf16.bf16.f32 "              \
        "{%0,%1,%2,%3},{%4,%5,%6,%7},{%8,%9},{%0,%1,%2,%3};"                \
        : "+f"((D)[0]), "+f"((D)[1]), "+f"((D)[2]), "+f"((D)[3])            \
        : "r"((A)[0]), "r"((A)[1]), "r"((A)[2]), "r"((A)[3]),               \
          "r"((B)[0]), "r"((B)[1]))

// ---------------- zero compact scratch + slot init ----------------
__global__ void zero_kernel() {
    int stride = gridDim.x * blockDim.x;
    int tid = blockIdx.x * blockDim.x + threadIdx.x;
    int total4 = BATCH * (GNN_DIM / 4);
    float4* a4 = reinterpret_cast<float4*>(g_aggrc);
    for (int i = tid; i < total4; i += stride)
        a4[i] = make_float4(0.f, 0.f, 0.f, 0.f);
    for (int i = tid; i < N_NODES; i += stride)
        g_slot[i] = -1;
}

__global__ void mark_kernel(const int* __restrict__ idx) {
    int b = blockIdx.x * blockDim.x + threadIdx.x;
    if (b < BATCH) {
        int n = idx[b];
        if (n >= 0) atomicCAS(&g_slot[n], -1, b);
    }
}

// ---------------- filtered edge scatter-add into compact buffer ----------------
__global__ void edge_kernel(const int* __restrict__ ei, const float* __restrict__ ew,
                            const float* __restrict__ x0) {
    const int lane = threadIdx.x & 31;
    const int warp = (blockIdx.x * blockDim.x + threadIdx.x) >> 5;
    const int e0 = warp * 32;
    if (e0 >= N_EDGES) return;
    const int e = e0 + lane;
    int sl = -1, s = 0; float w = 0.f;
    if (e < N_EDGES) {
        int d = ei[N_EDGES + e];
        sl = g_slot[d];
        if (sl >= 0) { s = ei[e]; w = ew[e]; }
    }
    unsigned mask = __ballot_sync(0xffffffffu, sl >= 0);
    while (mask) {
        int b = __ffs(mask) - 1; mask &= (mask - 1);
        int   ss = __shfl_sync(0xffffffffu, s, b);
        int   dd = __shfl_sync(0xffffffffu, sl, b);
        float ww = __shfl_sync(0xffffffffu, w, b);
        const float4* xr = reinterpret_cast<const float4*>(x0 + (size_t)ss * GNN_DIM);
        float* ar = g_aggrc + (size_t)dd * GNN_DIM;
        #pragma unroll
        for (int i = 0; i < 2; i++) {
            int c = lane + i * 32;
            float4 v = xr[c];
            asm volatile("red.global.add.v4.f32 [%0], {%1,%2,%3,%4};"
                         :: "l"(ar + c * 4), "f"(v.x * ww), "f"(v.y * ww),
                            "f"(v.z * ww), "f"(v.w * ww) : "memory");
        }
    }
}

// ---------------- fused: fold weights + bc + W_in split (ILP fixed) ---------
__global__ void fused_wc_kernel(const float* __restrict__ Wr, const float* __restrict__ Wn,
                                const float* __restrict__ Wp,
                                const float* __restrict__ bmp, const float* __restrict__ bpost,
                                const float* __restrict__ Win) {
    int bx = blockIdx.x, j = threadIdx.x;
    if (bx < GNN_DIM) {
        __shared__ float r[GNN_DIM], nn[GNN_DIM];
        r[j]  = Wr[bx * GNN_DIM + j] + (bx == j ? 1.f : 0.f);
        nn[j] = Wn[bx * GNN_DIM + j];
        __syncthreads();
        float a1[4] = {0, 0, 0, 0}, a2[4] = {0, 0, 0, 0};
        #pragma unroll 2
        for (int k = 0; k < GNN_DIM; k += 4) {
            #pragma unroll
            for (int u = 0; u < 4; u++) {
                float wp = Wp[(k + u) * GNN_DIM + j];
                a1[u] += r[k + u] * wp;
                a2[u] += nn[k + u] * wp;
            }
        }
        g_Wc1[bx * GNN_DIM + j] = (a1[0] + a1[1]) + (a1[2] + a1[3]);
        g_Wc2[bx * GNN_DIM + j] = (a2[0] + a2[1]) + (a2[2] + a2[3]);
    } else if (bx == GNN_DIM) {
        float a[4] = {bpost[j], 0, 0, 0};
        #pragma unroll 2
        for (int k = 0; k < GNN_DIM; k += 4) {
            #pragma unroll
            for (int u = 0; u < 4; u++)
                a[u] += bmp[k + u] * Wp[(k + u) * GNN_DIM + j];
        }
        g_bc[j] = (a[0] + a[1]) + (a[2] + a[3]);
    } else {
        int i = (bx - GNN_DIM - 1) * 256 + j;   // float4 index, 32768 total
        float4 v = reinterpret_cast<const float4*>(Win)[i];
        __nv_bfloat16 h0, l0, h1, l1, h2, l2, h3, l3;
        split2(v.x, h0, l0); split2(v.y, h1, l1);
        split2(v.z, h2, l2); split2(v.w, h3, l3);
        __nv_bfloat162* ph = reinterpret_cast<__nv_bfloat162*>(g_Winh) + i * 2;
        __nv_bfloat162* pl = reinterpret_cast<__nv_bfloat162*>(g_Winl) + i * 2;
        ph[0] = __nv_bfloat162{h0, h1}; ph[1] = __nv_bfloat162{h2, h3};
        pl[0] = __nv_bfloat162{l0, l1}; pl[1] = __nv_bfloat162{l2, l3};
    }
}

// ---------------- per-batch-row node transform -> split pert ----------------
__global__ void pert_kernel(const int* __restrict__ idx, const float* __restrict__ x0,
                            const float* __restrict__ fb) {
    constexpr int RPB = 8;
    __shared__ float xr[RPB][GNN_DIM];
    __shared__ float ar[RPB][GNN_DIM];
    __shared__ int   ns[RPB], sl[RPB];
    int j = threadIdx.x;
    int b0 = blockIdx.x * RPB;
    if (j < RPB) {
        int n = idx[b0 + j];
        ns[j] = n;
        sl[j] = (n >= 0) ? g_slot[n] : 0;
    }
    __syncthreads();
    #pragma unroll
    for (int r = 0; r < RPB; r++) {
        int n = ns[r]; int sn = (n < 0) ? 0 : n;
        xr[r][j] = x0[(size_t)sn * GNN_DIM + j];
        ar[r][j] = g_aggrc[(size_t)sl[r] * GNN_DIM + j];
    }
    __syncthreads();
    float acc[RPB];
    #pragma unroll
    for (int r = 0; r < RPB; r++) acc[r] = g_bc[j];
    for (int k = 0; k < GNN_DIM; k++) {
        float w1 = g_Wc1[k * GNN_DIM + j];
        float w2 = g_Wc2[k * GNN_DIM + j];
        #pragma unroll
        for (int r = 0; r < RPB; r++)
            acc[r] += xr[r][k] * w1 + ar[r][k] * w2;
    }
    float fbj = fb[j];
    #pragma unroll
    for (int r = 0; r < RPB; r++) {
        float v = (ns[r] >= 0) ? acc[r] : fbj;
        __nv_bfloat16 h, l; split2(v, h, l);
        g_perth[(size_t)(b0 + r) * GNN_DIM + j] = h;
        g_pertl[(size_t)(b0 + r) * GNN_DIM + j] = l;
    }
}

// ---------------- layernorm -> split xn ----------------
__global__ void ln_kernel(const float* __restrict__ hbuf, const float* __restrict__ g,
                          const float* __restrict__ bb) {
    int row = blockIdx.x;
    const float* x = hbuf + (size_t)row * HEAD_DIM;
    int tid = threadIdx.x;   // 128
    float v[4]; float s = 0.f, s2 = 0.f;
    #pragma unroll
    for (int i = 0; i < 4; i++) {
        v[i] = x[tid + i * 128];
        s += v[i]; s2 += v[i] * v[i];
    }
    #pragma unroll
    for (int o = 16; o; o >>= 1) {
        s  += __shfl_down_sync(0xffffffffu, s, o);
        s2 += __shfl_down_sync(0xffffffffu, s2, o);
    }
    __shared__ float ss[4], ss2[4];
    if ((tid & 31) == 0) { ss[tid >> 5] = s; ss2[tid >> 5] = s2; }
    __syncthreads();
    s  = ss[0] + ss[1] + ss[2] + ss[3];
    s2 = ss2[0] + ss2[1] + ss2[2] + ss2[3];
    float mu  = s * (1.f / HEAD_DIM);
    float var = s2 * (1.f / HEAD_DIM) - mu * mu;
    float rs  = rsqrtf(var + 1e-5f);
    #pragma unroll
    for (int i = 0; i < 4; i++) {
        int j = tid + i * 128;
        float o = (v[i] - mu) * rs * g[j] + bb[j];
        __nv_bfloat16 hh, ll; split2(o, hh, ll);
        g_xnh[(size_t)row * HEAD_DIM + j] = hh;
        g_xnl[(size_t)row * HEAD_DIM + j] = ll;
    }
}

// ---------------- fp32 -> bf16 hi/lo split (weights) ----------------
__global__ void split_kernel(const float* __restrict__ src,
                             __nv_bfloat16* __restrict__ dh,
                             __nv_bfloat16* __restrict__ dl, int n4) {
    int stride = gridDim.x * blockDim.x;
    for (int i = blockIdx.x * blockDim.x + threadIdx.x; i < n4; i += stride) {
        float4 v = reinterpret_cast<const float4*>(src)[i];
        __nv_bfloat16 h0, l0, h1, l1, h2, l2, h3, l3;
        split2(v.x, h0, l0); split2(v.y, h1, l1);
        split2(v.z, h2, l2); split2(v.w, h3, l3);
        __nv_bfloat162* ph = reinterpret_cast<__nv_bfloat162*>(dh) + i * 2;
        __nv_bfloat162* pl = reinterpret_cast<__nv_bfloat162*>(dl) + i * 2;
        ph[0] = __nv_bfloat162{h0, h1}; ph[1] = __nv_bfloat162{h2, h3};
        pl[0] = __nv_bfloat162{l0, l1}; pl[1] = __nv_bfloat162{l2, l3};
    }
}

// ================= bf16x3 tensor-core GEMM (128x128x32, occ2, multi-stage) ===
constexpr int BM = 128, BN = 128, BK = 32;
constexpr int ASTR = BK + 8;        // 40
constexpr int BSTR = BN + 8;        // 136

template<int STAGES, bool TRANSB>
struct GC {
    static constexpr int AE = 128 * ASTR;                    // 5120
    static constexpr int BE = TRANSB ? 128 * ASTR : 32 * BSTR; // 5120 / 4352
    static constexpr int SE = 2 * AE + 2 * BE;               // per-stage elems
    static constexpr int SMEM = STAGES * SE * 2;             // bytes
};
// non-TRANSB: 3 stages -> 113664 B (occ2 fits: <=116736)
// TRANSB:     2 stages ->  81920 B (occ2)

template<int STAGES, bool TRANSB>
__device__ __forceinline__ void load_stage(
    __nv_bfloat16* sm, int stage, int k0,
    const __nv_bfloat16* Ah, const __nv_bfloat16* Al,
    const __nv_bfloat16* Bh, const __nv_bfloat16* Bl,
    int N, int K, int crow, int ccol, int tid)
{
    using C = GC<STAGES, TRANSB>;
    __nv_bfloat16* base = sm + stage * C::SE;
    __nv_bfloat16* As_h = base;
    __nv_bfloat16* As_l = base + C::AE;
    __nv_bfloat16* Bs_h = base + 2 * C::AE;
    __nv_bfloat16* Bs_l = base + 2 * C::AE + C::BE;
    #pragma unroll
    for (int i = 0; i < 2; i++) {
        int q = tid + i * 256;
        int row = q >> 2, c8 = (q & 3) * 8;
        size_t goff = (size_t)(crow + row) * K + k0 + c8;
        uint32_t soff = row * ASTR + c8;
        cp16(smem_u32(As_h + soff), Ah + goff, true);
        cp16(smem_u32(As_l + soff), Al + goff, true);
    }
    if (!TRANSB) {
        #pragma unroll
        for (int i = 0; i < 2; i++) {
            int q = tid + i * 256;
            int row = q >> 4, c8 = (q & 15) * 8;
            size_t goff = (size_t)(k0 + row) * N + ccol + c8;
            uint32_t soff = row * BSTR + c8;
            cp16(smem_u32(Bs_h + soff), Bh + goff, true);
            cp16(smem_u32(Bs_l + soff), Bl + goff, true);
        }
    } else {
        #pragma unroll
        for (int i = 0; i < 2; i++) {
            int q = tid + i * 256;
            int row = q >> 2, c8 = (q & 3) * 8;
            bool ok = (ccol + row) < N;
            size_t goff = ok ? ((size_t)(ccol + row) * K + k0 + c8) : 0;
            uint32_t soff = row * ASTR + c8;
            cp16(smem_u32(Bs_h + soff), Bh + goff, ok);
            cp16(smem_u32(Bs_l + soff), Bl + goff, ok);
        }
    }
}

__device__ __forceinline__ void load_afrag(uint32_t a[4][4], const __nv_bfloat16* As,
                                           int warpM, int lane, int kk) {
    int lrow = warpM + (lane & 15);
    int lcol = kk + ((lane >> 4) << 3);
    #pragma unroll
    for (int mt = 0; mt < 4; mt++)
        ldm_x4(a[mt], smem_u32(As + (lrow + mt * 16) * ASTR + lcol));
}

template<bool TRANSB>
__device__ __forceinline__ void load_bfrag(uint32_t b[4][2], const __nv_bfloat16* Bs,
                                           int warpN, int lane, int kk) {
    int j = lane >> 3, r8 = lane & 7;
    if (!TRANSB) {
        int krow = kk + r8 + ((j & 1) << 3);
        #pragma unroll
        for (int np = 0; np < 2; np++) {
            int ncol = warpN + np * 16 + ((j >> 1) << 3);
            uint32_t r[4];
            ldm_x4_t(r, smem_u32(Bs + krow * BSTR + ncol));
            b[np * 2][0] = r[0]; b[np * 2][1] = r[1];
            b[np * 2 + 1][0] = r[2]; b[np * 2 + 1][1] = r[3];
        }
    } else {
        int kcol = kk + ((j & 1) << 3);
        #pragma unroll
        for (int np = 0; np < 2; np++) {
            int nrow = warpN + np * 16 + r8 + ((j >> 1) << 3);
            uint32_t r[4];
            ldm_x4(r, smem_u32(Bs + nrow * ASTR + kcol));
            b[np * 2][0] = r[0]; b[np * 2][1] = r[1];
            b[np * 2 + 1][0] = r[2]; b[np * 2 + 1][1] = r[3];
        }
    }
}

template<int STAGES, bool TRANSB, bool BIAS, bool GELU, bool SPLITOUT, bool RESID>
__global__ void __launch_bounds__(256, 2) gemm_bf3(
    int M, int N, int K,
    const __nv_bfloat16* __restrict__ Ah, const __nv_bfloat16* __restrict__ Al,
    const __nv_bfloat16* __restrict__ Bh, const __nv_bfloat16* __restrict__ Bl,
    const float* __restrict__ bias, float* __restrict__ C,
    __nv_bfloat16* __restrict__ Oh, __nv_bfloat16* __restrict__ Ol)
{
    using CF = GC<STAGES, TRANSB>;
    extern __shared__ __nv_bfloat16 sm[];
    const int tid  = threadIdx.x;
    const int lane = tid & 31;
    const int warp = tid >> 5;
    const int crow = blockIdx.y * BM;
    const int ccol = blockIdx.x * BN;
    const int warpM = (warp >> 2) * 64;
    const int warpN = (warp & 3) * 32;
    const int r = lane >> 2, c = lane & 3;

    float acc[4][4][4];
    #pragma unroll
    for (int mt = 0; mt < 4; mt++)
        #pragma unroll
        for (int nt = 0; nt < 4; nt++)
            #pragma unroll
            for (int i = 0; i < 4; i++) acc[mt][nt][i] = 0.f;

    const int KT = K / BK;

    auto compute_stage = [&](int st) {
        const __nv_bfloat16* base = sm + st * CF::SE;
        const __nv_bfloat16* As_h = base;
        const __nv_bfloat16* As_l = base + CF::AE;
        const __nv_bfloat16* Bs_h = base + 2 * CF::AE;
        const __nv_bfloat16* Bs_l = base + 2 * CF::AE + CF::BE;
        #pragma unroll
        for (int ks = 0; ks < 2; ks++) {
            const int kk = ks * 16;
            uint32_t ah[4][4], al[4][4], bh[4][2], bl[4][2];
            load_afrag(ah, As_h, warpM, lane, kk);
            load_bfrag<TRANSB>(bh, Bs_h, warpN, lane, kk);
            #pragma unroll
            for (int mt = 0; mt < 4; mt++)
                #pragma unroll
                for (int nt = 0; nt < 4; nt++)
                    MMA_BF16(acc[mt][nt], ah[mt], bh[nt]);
            load_afrag(al, As_l, warpM, lane, kk);
            #pragma unroll
            for (int mt = 0; mt < 4; mt++)
                #pragma unroll
                for (int nt = 0; nt < 4; nt++)
                    MMA_BF16(acc[mt][nt], al[mt], bh[nt]);
            load_bfrag<TRANSB>(bl, Bs_l, warpN, lane, kk);
            #pragma unroll
            for (int mt = 0; mt < 4; mt++)
                #pragma unroll
                for (int nt = 0; nt < 4; nt++)
                    MMA_BF16(acc[mt][nt], ah[mt], bl[nt]);
        }
    };

    if constexpr (STAGES == 3) {
        // prologue: stages 0 and 1 (KT >= 8 at all call sites)
        load_stage<STAGES, TRANSB>(sm, 0, 0, Ah, Al, Bh, Bl, N, K, crow, ccol, tid);
        asm volatile("cp.async.commit_group;" ::: "memory");
        load_stage<STAGES, TRANSB>(sm, 1, BK, Ah, Al, Bh, Bl, N, K, crow, ccol, tid);
        asm volatile("cp.async.commit_group;" ::: "memory");
        for (int kt = 0; kt < KT; kt++) {
            asm volatile("cp.async.wait_group 1;" ::: "memory");
            __syncthreads();
            if (kt + 2 < KT)
                load_stage<STAGES, TRANSB>(sm, (kt + 2) % 3, (kt + 2) * BK,
                                           Ah, Al, Bh, Bl, N, K, crow, ccol, tid);
            asm volatile("cp.async.commit_group;" ::: "memory");  // maybe empty
            compute_stage(kt % 3);
        }
    } else {
        load_stage<STAGES, TRANSB>(sm, 0, 0, Ah, Al, Bh, Bl, N, K, crow, ccol, tid);
        asm volatile("cp.async.commit_group;" ::: "memory");
        for (int kt = 0; kt < KT; kt++) {
            if (kt + 1 < KT) {
                load_stage<STAGES, TRANSB>(sm, (kt + 1) & 1, (kt + 1) * BK,
                                           Ah, Al, Bh, Bl, N, K, crow, ccol, tid);
                asm volatile("cp.async.commit_group;" ::: "memory");
                asm volatile("cp.async.wait_group 1;" ::: "memory");
            } else {
                asm volatile("cp.async.wait_group 0;" ::: "memory");
            }
            __syncthreads();
            compute_stage(kt & 1);
            __syncthreads();
        }
    }

    // ---- epilogue ----
    #pragma unroll
    for (int mt = 0; mt < 4; mt++) {
        #pragma unroll
        for (int nt = 0; nt < 4; nt++) {
            int m0 = crow + warpM + mt * 16;
            int n0 = ccol + warpN + nt * 8;
            #pragma unroll
            for (int half = 0; half < 2; half++) {
                int m = m0 + r + half * 8;
                int n = n0 + c * 2;
                if (n >= N) continue;
                float v0 = acc[mt][nt][half * 2 + 0];
                float v1 = acc[mt][nt][half * 2 + 1];
                if (BIAS) { v0 += bias[n]; v1 += bias[n + 1]; }
                if (GELU) { v0 = gelu_exact(v0); v1 = gelu_exact(v1); }
                if (RESID) {
                    float2 o = *reinterpret_cast<float2*>(C + (size_t)m * N + n);
                    v0 += o.x; v1 += o.y;
                }
                if (SPLITOUT) {
                    __nv_bfloat16 h0, l0, h1, l1;
                    split2(v0, h0, l0); split2(v1, h1, l1);
                    *reinterpret_cast<__nv_bfloat162*>(Oh + (size_t)m * N + n) =
                        __nv_bfloat162{h0, h1};
                    *reinterpret_cast<__nv_bfloat162*>(Ol + (size_t)m * N + n) =
                        __nv_bfloat162{l0, l1};
                } else {
                    *reinterpret_cast<float2*>(C + (size_t)m * N + n) =
                        make_float2(v0, v1);
                }
            }
        }
    }
}

constexpr int SM_NT = GC<3, false>::SMEM;   // 113664
constexpr int SM_TR = GC<2, true>::SMEM;    // 81920

// ---------------- launch ----------------
extern "C" void kernel_launch(void* const* d_in, const int* in_sizes, int n_in,
                              void* d_out, int out_size) {
    const int*   node_idx  = (const int*)  d_in[0];
    const int*   edge_idx  = (const int*)  d_in[1];
    const float* edge_w    = (const float*)d_in[2];
    const float* frozen    = (const float*)d_in[3];
    const float* W_root    = (const float*)d_in[4];
    const float* W_nbr     = (const float*)d_in[5];
    const float* b_mp      = (const float*)d_in[6];
    const float* W_post    = (const float*)d_in[7];
    const float* b_post    = (const float*)d_in[8];
    const float* fallback  = (const float*)d_in[9];
    const float* W_in      = (const float*)d_in[10];
    const float* b_in      = (const float*)d_in[11];
    const float* ln_g      = (const float*)d_in[12];
    const float* ln_b      = (const float*)d_in[13];
    const float* W1        = (const float*)d_in[14];
    const float* b1        = (const float*)d_in[15];
    const float* W2        = (const float*)d_in[16];
    const float* W_bil     = (const float*)d_in[17];
    const float* out_emb   = (const float*)d_in[18];
    float*       logits    = (float*)d_out;

    float *p_h;
    cudaGetSymbolAddress((void**)&p_h, g_h);
    __nv_bfloat16 *p_perth, *p_pertl, *p_xnh, *p_xnl, *p_acth, *p_actl;
    __nv_bfloat16 *p_hsh, *p_hsl, *p_projh, *p_projl;
    __nv_bfloat16 *p_Winh, *p_Winl, *p_W1h, *p_W1l, *p_W2h, *p_W2l;
    __nv_bfloat16 *p_bilh, *p_bill, *p_oeh, *p_oel;
    cudaGetSymbolAddress((void**)&p_perth, g_perth);
    cudaGetSymbolAddress((void**)&p_pertl, g_pertl);
    cudaGetSymbolAddress((void**)&p_xnh,  g_xnh);
    cudaGetSymbolAddress((void**)&p_xnl,  g_xnl);
    cudaGetSymbolAddress((void**)&p_acth, g_acth);
    cudaGetSymbolAddress((void**)&p_actl, g_actl);
    cudaGetSymbolAddress((void**)&p_hsh,  g_hsh);
    cudaGetSymbolAddress((void**)&p_hsl,  g_hsl);
    cudaGetSymbolAddress((void**)&p_projh, g_projh);
    cudaGetSymbolAddress((void**)&p_projl, g_projl);
    cudaGetSymbolAddress((void**)&p_Winh, g_Winh);
    cudaGetSymbolAddress((void**)&p_Winl, g_Winl);
    cudaGetSymbolAddress((void**)&p_W1h,  g_W1h);
    cudaGetSymbolAddress((void**)&p_W1l,  g_W1l);
    cudaGetSymbolAddress((void**)&p_W2h,  g_W2h);
    cudaGetSymbolAddress((void**)&p_W2l,  g_W2l);
    cudaGetSymbolAddress((void**)&p_bilh, g_bilh);
    cudaGetSymbolAddress((void**)&p_bill, g_bill);
    cudaGetSymbolAddress((void**)&p_oeh,  g_oeh);
    cudaGetSymbolAddress((void**)&p_oel,  g_oel);

    cudaFuncSetAttribute(gemm_bf3<3, false, true,  true,  false, false>,
        cudaFuncAttributeMaxDynamicSharedMemorySize, SM_NT);
    cudaFuncSetAttribute(gemm_bf3<3, false, true,  true,  true,  false>,
        cudaFuncAttributeMaxDynamicSharedMemorySize, SM_NT);
    cudaFuncSetAttribute(gemm_bf3<3, false, false, false, false, true>,
        cudaFuncAttributeMaxDynamicSharedMemorySize, SM_NT);
    cudaFuncSetAttribute(gemm_bf3<3, false, false, false, true,  true>,
        cudaFuncAttributeMaxDynamicSharedMemorySize, SM_NT);
    cudaFuncSetAttribute(gemm_bf3<3, false, false, false, true,  false>,
        cudaFuncAttributeMaxDynamicSharedMemorySize, SM_NT);
    cudaFuncSetAttribute(gemm_bf3<2, true,  false, false, false, false>,
        cudaFuncAttributeMaxDynamicSharedMemorySize, SM_TR);

    // --- launch order: index 3 = edge_kernel (ncu captures launch #3) ---
    zero_kernel<<<512, 256>>>();                               // 0
    mark_kernel<<<(BATCH + 255) / 256, 256>>>(node_idx);       // 1
    fused_wc_kernel<<<GNN_DIM + 1 + 128, GNN_DIM>>>(           // 2
        W_root, W_nbr, W_post, b_mp, b_post, W_in);
    {
        int warps = (N_EDGES + 31) / 32;
        int blocks = (warps + 7) / 8;
        edge_kernel<<<blocks, 256>>>(edge_idx, edge_w, frozen);  // 3 <-- profiled
    }
    pert_kernel<<<BATCH / 8, GNN_DIM>>>(node_idx, frozen, fallback);  // 4

    // h = gelu(pert @ W_in + b_in)
    {
        dim3 grid(HEAD_DIM / BN, BATCH / BM);
        gemm_bf3<3, false, true, true, false, false><<<grid, 256, SM_NT>>>(
            BATCH, HEAD_DIM, GNN_DIM, p_perth, p_pertl, p_Winh, p_Winl,
            b_in, p_h, nullptr, nullptr);
    }

    // remaining weight splits (before their consumers)
    split_kernel<<<2048, 256>>>(W1,    p_W1h,  p_W1l,  N_RES * HEAD_DIM * FF_DIM / 4);
    split_kernel<<<2048, 256>>>(W2,    p_W2h,  p_W2l,  N_RES * FF_DIM * HEAD_DIM / 4);
    split_kernel<<<512, 256>>>(W_bil,  p_bilh, p_bill, HEAD_DIM * BIL_DIM / 4);
    split_kernel<<<1024, 256>>>(out_emb, p_oeh, p_oel, N_GENES * HEAD_DIM / 4);

    for (int i = 0; i < N_RES; i++) {
        ln_kernel<<<BATCH, 128>>>(p_h, ln_g + (size_t)i * HEAD_DIM,
                                  ln_b + (size_t)i * HEAD_DIM);
        dim3 g1(FF_DIM / BN, BATCH / BM);
        gemm_bf3<3, false, true, true, true, false><<<g1, 256, SM_NT>>>(
            BATCH, FF_DIM, HEAD_DIM, p_xnh, p_xnl,
            p_W1h + (size_t)i * HEAD_DIM * FF_DIM, p_W1l + (size_t)i * HEAD_DIM * FF_DIM,
            b1 + (size_t)i * FF_DIM, nullptr, p_acth, p_actl);
        dim3 g2(HEAD_DIM / BN, BATCH / BM);
        if (i < N_RES - 1) {
            gemm_bf3<3, false, false, false, false, true><<<g2, 256, SM_NT>>>(
                BATCH, HEAD_DIM, FF_DIM, p_acth, p_actl,
                p_W2h + (size_t)i * FF_DIM * HEAD_DIM, p_W2l + (size_t)i * FF_DIM * HEAD_DIM,
                nullptr, p_h, nullptr, nullptr);
        } else {
            gemm_bf3<3, false, false, false, true, true><<<g2, 256, SM_NT>>>(
                BATCH, HEAD_DIM, FF_DIM, p_acth, p_actl,
                p_W2h + (size_t)i * FF_DIM * HEAD_DIM, p_W2l + (size_t)i * FF_DIM * HEAD_DIM,
                nullptr, p_h, p_hsh, p_hsl);
        }
    }
    // proj = h @ W_bil (split output)
    {
        dim3 grid(BIL_DIM / BN, BATCH / BM);
        gemm_bf3<3, false, false, false, true, false><<<grid, 256, SM_NT>>>(
            BATCH, BIL_DIM, HEAD_DIM, p_hsh, p_hsl, p_bilh, p_bill,
            nullptr, nullptr, p_projh, p_projl);
    }
    // logits = reshape(proj,[B*3,512]) @ out_emb^T
    {
        dim3 grid((N_GENES + BN - 1) / BN, (BATCH * N_CLASSES) / BM);
        gemm_bf3<2, true, false, false, false, false><<<grid, 256, SM_TR>>>(
            BATCH * N_CLASSES, N_GENES, HEAD_DIM, p_projh, p_projl, p_oeh, p_oel,
            nullptr, logits, nullptr, nullptr);
    }
}

// round 13
// speedup vs baseline: 1.6736x; 1.2074x over previous
#include <cuda_runtime.h>
#include <cuda_bf16.h>
#include <math.h>
#include <stdint.h>

// ---------------- problem constants ----------------
#define N_NODES   19385
#define N_EDGES   1200000
#define GNN_DIM   256
#define HEAD_DIM  512
#define EXPAND    4
#define N_CLASSES 3
#define N_GENES   6640
#define N_RES     6
#define BATCH     2048
#define FF_DIM    (HEAD_DIM * EXPAND)    // 2048
#define BIL_DIM   (N_CLASSES * HEAD_DIM) // 1536

// ---------------- fp32 scratch ----------------
__device__ float g_aggrc[(size_t)BATCH * GNN_DIM];
__device__ int   g_slot[N_NODES];
__device__ float g_Wc1[GNN_DIM * GNN_DIM];
__device__ float g_Wc2[GNN_DIM * GNN_DIM];
__device__ float g_bc[GNN_DIM];
__device__ float g_h[(size_t)BATCH * HEAD_DIM];

// ---------------- bf16 split scratch (hi/lo pairs) ----------------
__device__ __nv_bfloat16 g_perth[(size_t)BATCH * GNN_DIM];
__device__ __nv_bfloat16 g_pertl[(size_t)BATCH * GNN_DIM];
__device__ __nv_bfloat16 g_xnh[(size_t)BATCH * HEAD_DIM];
__device__ __nv_bfloat16 g_xnl[(size_t)BATCH * HEAD_DIM];
__device__ __nv_bfloat16 g_acth[(size_t)BATCH * FF_DIM];
__device__ __nv_bfloat16 g_actl[(size_t)BATCH * FF_DIM];
__device__ __nv_bfloat16 g_hsh[(size_t)BATCH * HEAD_DIM];
__device__ __nv_bfloat16 g_hsl[(size_t)BATCH * HEAD_DIM];
__device__ __nv_bfloat16 g_projh[(size_t)BATCH * BIL_DIM];
__device__ __nv_bfloat16 g_projl[(size_t)BATCH * BIL_DIM];
// weight splits ([K,N] layout)
__device__ __nv_bfloat16 g_Winh[GNN_DIM * HEAD_DIM];
__device__ __nv_bfloat16 g_Winl[GNN_DIM * HEAD_DIM];
__device__ __nv_bfloat16 g_W1h[(size_t)N_RES * HEAD_DIM * FF_DIM];
__device__ __nv_bfloat16 g_W1l[(size_t)N_RES * HEAD_DIM * FF_DIM];
__device__ __nv_bfloat16 g_W2h[(size_t)N_RES * FF_DIM * HEAD_DIM];
__device__ __nv_bfloat16 g_W2l[(size_t)N_RES * FF_DIM * HEAD_DIM];
__device__ __nv_bfloat16 g_bilh[HEAD_DIM * BIL_DIM];
__device__ __nv_bfloat16 g_bill[HEAD_DIM * BIL_DIM];
__device__ __nv_bfloat16 g_oeh[(size_t)N_GENES * HEAD_DIM];
__device__ __nv_bfloat16 g_oel[(size_t)N_GENES * HEAD_DIM];

// ---------------- helpers ----------------
__device__ __forceinline__ float gelu_exact(float v) {
    return 0.5f * v * (1.0f + erff(v * 0.70710678118654752f));
}
__device__ __forceinline__ void split2(float x, __nv_bfloat16& h, __nv_bfloat16& l) {
    h = __float2bfloat16_rn(x);
    l = __float2bfloat16_rn(x - __bfloat162float(h));
}
__device__ __forceinline__ uint32_t smem_u32(const void* p) {
    return (uint32_t)__cvta_generic_to_shared(p);
}
__device__ __forceinline__ void cp16(uint32_t dst, const void* src, bool pred) {
    int sz = pred ? 16 : 0;
    asm volatile("cp.async.cg.shared.global [%0], [%1], 16, %2;\n"
                 :: "r"(dst), "l"(src), "r"(sz));
}
__device__ __forceinline__ void ldm_x4(uint32_t* r, uint32_t addr) {
    asm volatile("ldmatrix.sync.aligned.m8n8.x4.shared.b16 {%0,%1,%2,%3}, [%4];"
                 : "=r"(r[0]), "=r"(r[1]), "=r"(r[2]), "=r"(r[3]) : "r"(addr));
}
__device__ __forceinline__ void ldm_x4_t(uint32_t* r, uint32_t addr) {
    asm volatile("ldmatrix.sync.aligned.m8n8.x4.trans.shared.b16 {%0,%1,%2,%3}, [%4];"
                 : "=r"(r[0]), "=r"(r[1]), "=r"(r[2]), "=r"(r[3]) : "r"(addr));
}
#define MMA_BF16(D, A, B)                                                   \
    asm volatile(                                                           \
        "mma.sync.aligned.m16n8k16.row.col.f32.bf16.bf16.f32 "              \
        "{%0,%1,%2,%3},{%4,%5,%6,%7},{%8,%9},{%0,%1,%2,%3};"                \
        : "+f"((D)[0]), "+f"((D)[1]), "+f"((D)[2]), "+f"((D)[3])            \
        : "r"((A)[0]), "r"((A)[1]), "r"((A)[2]), "r"((A)[3]),               \
          "r"((B)[0]), "r"((B)[1]))

// ---------------- zero compact scratch + slot init ----------------
__global__ void zero_kernel() {
    int stride = gridDim.x * blockDim.x;
    int tid = blockIdx.x * blockDim.x + threadIdx.x;
    int total4 = BATCH * (GNN_DIM / 4);
    float4* a4 = reinterpret_cast<float4*>(g_aggrc);
    for (int i = tid; i < total4; i += stride)
        a4[i] = make_float4(0.f, 0.f, 0.f, 0.f);
    for (int i = tid; i < N_NODES; i += stride)
        g_slot[i] = -1;
}

__global__ void mark_kernel(const int* __restrict__ idx) {
    int b = blockIdx.x * blockDim.x + threadIdx.x;
    if (b < BATCH) {
        int n = idx[b];
        if (n >= 0) atomicCAS(&g_slot[n], -1, b);
    }
}

// ---------------- filtered edge scatter-add into compact buffer ----------------
__global__ void edge_kernel(const int* __restrict__ ei, const float* __restrict__ ew,
                            const float* __restrict__ x0) {
    const int lane = threadIdx.x & 31;
    const int warp = (blockIdx.x * blockDim.x + threadIdx.x) >> 5;
    const int e0 = warp * 32;
    if (e0 >= N_EDGES) return;
    const int e = e0 + lane;
    int sl = -1, s = 0; float w = 0.f;
    if (e < N_EDGES) {
        int d = ei[N_EDGES + e];
        sl = g_slot[d];
        if (sl >= 0) { s = ei[e]; w = ew[e]; }
    }
    unsigned mask = __ballot_sync(0xffffffffu, sl >= 0);
    while (mask) {
        int b = __ffs(mask) - 1; mask &= (mask - 1);
        int   ss = __shfl_sync(0xffffffffu, s, b);
        int   dd = __shfl_sync(0xffffffffu, sl, b);
        float ww = __shfl_sync(0xffffffffu, w, b);
        const float4* xr = reinterpret_cast<const float4*>(x0 + (size_t)ss * GNN_DIM);
        float* ar = g_aggrc + (size_t)dd * GNN_DIM;
        #pragma unroll
        for (int i = 0; i < 2; i++) {
            int c = lane + i * 32;
            float4 v = xr[c];
            asm volatile("red.global.add.v4.f32 [%0], {%1,%2,%3,%4};"
                         :: "l"(ar + c * 4), "f"(v.x * ww), "f"(v.y * ww),
                            "f"(v.z * ww), "f"(v.w * ww) : "memory");
        }
    }
}

// ---------------- fused: fold weights + bc + W_in split ----------------
__global__ void fused_wc_kernel(const float* __restrict__ Wr, const float* __restrict__ Wn,
                                const float* __restrict__ Wp,
                                const float* __restrict__ bmp, const float* __restrict__ bpost,
                                const float* __restrict__ Win) {
    int bx = blockIdx.x, j = threadIdx.x;
    if (bx < GNN_DIM) {
        __shared__ float r[GNN_DIM], nn[GNN_DIM];
        r[j]  = Wr[bx * GNN_DIM + j] + (bx == j ? 1.f : 0.f);
        nn[j] = Wn[bx * GNN_DIM + j];
        __syncthreads();
        float a1[4] = {0, 0, 0, 0}, a2[4] = {0, 0, 0, 0};
        #pragma unroll 2
        for (int k = 0; k < GNN_DIM; k += 4) {
            #pragma unroll
            for (int u = 0; u < 4; u++) {
                float wp = Wp[(k + u) * GNN_DIM + j];
                a1[u] += r[k + u] * wp;
                a2[u] += nn[k + u] * wp;
            }
        }
        g_Wc1[bx * GNN_DIM + j] = (a1[0] + a1[1]) + (a1[2] + a1[3]);
        g_Wc2[bx * GNN_DIM + j] = (a2[0] + a2[1]) + (a2[2] + a2[3]);
    } else if (bx == GNN_DIM) {
        float a[4] = {bpost[j], 0, 0, 0};
        #pragma unroll 2
        for (int k = 0; k < GNN_DIM; k += 4) {
            #pragma unroll
            for (int u = 0; u < 4; u++)
                a[u] += bmp[k + u] * Wp[(k + u) * GNN_DIM + j];
        }
        g_bc[j] = (a[0] + a[1]) + (a[2] + a[3]);
    } else {
        int i = (bx - GNN_DIM - 1) * 256 + j;
        float4 v = reinterpret_cast<const float4*>(Win)[i];
        __nv_bfloat16 h0, l0, h1, l1, h2, l2, h3, l3;
        split2(v.x, h0, l0); split2(v.y, h1, l1);
        split2(v.z, h2, l2); split2(v.w, h3, l3);
        __nv_bfloat162* ph = reinterpret_cast<__nv_bfloat162*>(g_Winh) + i * 2;
        __nv_bfloat162* pl = reinterpret_cast<__nv_bfloat162*>(g_Winl) + i * 2;
        ph[0] = __nv_bfloat162{h0, h1}; ph[1] = __nv_bfloat162{h2, h3};
        pl[0] = __nv_bfloat162{l0, l1}; pl[1] = __nv_bfloat162{l2, l3};
    }
}

// ---------------- per-batch-row node transform -> split pert ----------------
__global__ void pert_kernel(const int* __restrict__ idx, const float* __restrict__ x0,
                            const float* __restrict__ fb) {
    constexpr int RPB = 8;
    __shared__ float xr[RPB][GNN_DIM];
    __shared__ float ar[RPB][GNN_DIM];
    __shared__ int   ns[RPB], sl[RPB];
    int j = threadIdx.x;
    int b0 = blockIdx.x * RPB;
    if (j < RPB) {
        int n = idx[b0 + j];
        ns[j] = n;
        sl[j] = (n >= 0) ? g_slot[n] : 0;
    }
    __syncthreads();
    #pragma unroll
    for (int r = 0; r < RPB; r++) {
        int n = ns[r]; int sn = (n < 0) ? 0 : n;
        xr[r][j] = x0[(size_t)sn * GNN_DIM + j];
        ar[r][j] = g_aggrc[(size_t)sl[r] * GNN_DIM + j];
    }
    __syncthreads();
    float acc[RPB];
    #pragma unroll
    for (int r = 0; r < RPB; r++) acc[r] = g_bc[j];
    for (int k = 0; k < GNN_DIM; k++) {
        float w1 = g_Wc1[k * GNN_DIM + j];
        float w2 = g_Wc2[k * GNN_DIM + j];
        #pragma unroll
        for (int r = 0; r < RPB; r++)
            acc[r] += xr[r][k] * w1 + ar[r][k] * w2;
    }
    float fbj = fb[j];
    #pragma unroll
    for (int r = 0; r < RPB; r++) {
        float v = (ns[r] >= 0) ? acc[r] : fbj;
        __nv_bfloat16 h, l; split2(v, h, l);
        g_perth[(size_t)(b0 + r) * GNN_DIM + j] = h;
        g_pertl[(size_t)(b0 + r) * GNN_DIM + j] = l;
    }
}

// ---------------- layernorm -> split xn ----------------
__global__ void ln_kernel(const float* __restrict__ hbuf, const float* __restrict__ g,
                          const float* __restrict__ bb) {
    int row = blockIdx.x;
    const float* x = hbuf + (size_t)row * HEAD_DIM;
    int tid = threadIdx.x;   // 128
    float v[4]; float s = 0.f, s2 = 0.f;
    #pragma unroll
    for (int i = 0; i < 4; i++) {
        v[i] = x[tid + i * 128];
        s += v[i]; s2 += v[i] * v[i];
    }
    #pragma unroll
    for (int o = 16; o; o >>= 1) {
        s  += __shfl_down_sync(0xffffffffu, s, o);
        s2 += __shfl_down_sync(0xffffffffu, s2, o);
    }
    __shared__ float ss[4], ss2[4];
    if ((tid & 31) == 0) { ss[tid >> 5] = s; ss2[tid >> 5] = s2; }
    __syncthreads();
    s  = ss[0] + ss[1] + ss[2] + ss[3];
    s2 = ss2[0] + ss2[1] + ss2[2] + ss2[3];
    float mu  = s * (1.f / HEAD_DIM);
    float var = s2 * (1.f / HEAD_DIM) - mu * mu;
    float rs  = rsqrtf(var + 1e-5f);
    #pragma unroll
    for (int i = 0; i < 4; i++) {
        int j = tid + i * 128;
        float o = (v[i] - mu) * rs * g[j] + bb[j];
        __nv_bfloat16 hh, ll; split2(o, hh, ll);
        g_xnh[(size_t)row * HEAD_DIM + j] = hh;
        g_xnl[(size_t)row * HEAD_DIM + j] = ll;
    }
}

// ---------------- fp32 -> bf16 hi/lo split (weights) ----------------
__global__ void split_kernel(const float* __restrict__ src,
                             __nv_bfloat16* __restrict__ dh,
                             __nv_bfloat16* __restrict__ dl, int n4) {
    int stride = gridDim.x * blockDim.x;
    for (int i = blockIdx.x * blockDim.x + threadIdx.x; i < n4; i += stride) {
        float4 v = reinterpret_cast<const float4*>(src)[i];
        __nv_bfloat16 h0, l0, h1, l1, h2, l2, h3, l3;
        split2(v.x, h0, l0); split2(v.y, h1, l1);
        split2(v.z, h2, l2); split2(v.w, h3, l3);
        __nv_bfloat162* ph = reinterpret_cast<__nv_bfloat162*>(dh) + i * 2;
        __nv_bfloat162* pl = reinterpret_cast<__nv_bfloat162*>(dl) + i * 2;
        ph[0] = __nv_bfloat162{h0, h1}; ph[1] = __nv_bfloat162{h2, h3};
        pl[0] = __nv_bfloat162{l0, l1}; pl[1] = __nv_bfloat162{l2, l3};
    }
}

// ================= bf16x3 tensor-core GEMM (BMx128x32, occ2, multi-stage) ====
constexpr int BN = 128, BK = 32;
constexpr int ASTR = BK + 8;        // 40
constexpr int BSTR = BN + 8;        // 136

template<int BM, int STAGES, bool TRANSB>
struct GC {
    static constexpr int AE = BM * ASTR;
    static constexpr int BE = TRANSB ? 128 * ASTR : 32 * BSTR;
    static constexpr int SE = 2 * AE + 2 * BE;
    static constexpr int SMEM = STAGES * SE * 2;
};
// BM=128 3-stage non-T: 113664 B (occ2 <=116736 ok)
// BM=64  3-stage non-T:  82944 B (occ2)
// BM=128 2-stage TRANSB: 81920 B (occ2)

template<int BM, int STAGES, bool TRANSB>
__device__ __forceinline__ void load_stage(
    __nv_bfloat16* sm, int stage, int k0,
    const __nv_bfloat16* Ah, const __nv_bfloat16* Al,
    const __nv_bfloat16* Bh, const __nv_bfloat16* Bl,
    int N, int K, int crow, int ccol, int tid)
{
    using C = GC<BM, STAGES, TRANSB>;
    __nv_bfloat16* base = sm + stage * C::SE;
    __nv_bfloat16* As_h = base;
    __nv_bfloat16* As_l = base + C::AE;
    __nv_bfloat16* Bs_h = base + 2 * C::AE;
    __nv_bfloat16* Bs_l = base + 2 * C::AE + C::BE;
    #pragma unroll
    for (int i = 0; i < BM / 64; i++) {
        int q = tid + i * 256;
        int row = q >> 2, c8 = (q & 3) * 8;
        size_t goff = (size_t)(crow + row) * K + k0 + c8;
        uint32_t soff = row * ASTR + c8;
        cp16(smem_u32(As_h + soff), Ah + goff, true);
        cp16(smem_u32(As_l + soff), Al + goff, true);
    }
    if (!TRANSB) {
        #pragma unroll
        for (int i = 0; i < 2; i++) {
            int q = tid + i * 256;
            int row = q >> 4, c8 = (q & 15) * 8;
            size_t goff = (size_t)(k0 + row) * N + ccol + c8;
            uint32_t soff = row * BSTR + c8;
            cp16(smem_u32(Bs_h + soff), Bh + goff, true);
            cp16(smem_u32(Bs_l + soff), Bl + goff, true);
        }
    } else {
        #pragma unroll
        for (int i = 0; i < 2; i++) {
            int q = tid + i * 256;
            int row = q >> 2, c8 = (q & 3) * 8;
            bool ok = (ccol + row) < N;
            size_t goff = ok ? ((size_t)(ccol + row) * K + k0 + c8) : 0;
            uint32_t soff = row * ASTR + c8;
            cp16(smem_u32(Bs_h + soff), Bh + goff, ok);
            cp16(smem_u32(Bs_l + soff), Bl + goff, ok);
        }
    }
}

template<int MT>
__device__ __forceinline__ void load_afrag(uint32_t a[MT][4], const __nv_bfloat16* As,
                                           int warpM, int lane, int kk) {
    int lrow = warpM + (lane & 15);
    int lcol = kk + ((lane >> 4) << 3);
    #pragma unroll
    for (int mt = 0; mt < MT; mt++)
        ldm_x4(a[mt], smem_u32(As + (lrow + mt * 16) * ASTR + lcol));
}

template<bool TRANSB>
__device__ __forceinline__ void load_bfrag(uint32_t b[4][2], const __nv_bfloat16* Bs,
                                           int warpN, int lane, int kk) {
    int j = lane >> 3, r8 = lane & 7;
    if (!TRANSB) {
        int krow = kk + r8 + ((j & 1) << 3);
        #pragma unroll
        for (int np = 0; np < 2; np++) {
            int ncol = warpN + np * 16 + ((j >> 1) << 3);
            uint32_t r[4];
            ldm_x4_t(r, smem_u32(Bs + krow * BSTR + ncol));
            b[np * 2][0] = r[0]; b[np * 2][1] = r[1];
            b[np * 2 + 1][0] = r[2]; b[np * 2 + 1][1] = r[3];
        }
    } else {
        int kcol = kk + ((j & 1) << 3);
        #pragma unroll
        for (int np = 0; np < 2; np++) {
            int nrow = warpN + np * 16 + r8 + ((j >> 1) << 3);
            uint32_t r[4];
            ldm_x4(r, smem_u32(Bs + nrow * ASTR + kcol));
            b[np * 2][0] = r[0]; b[np * 2][1] = r[1];
            b[np * 2 + 1][0] = r[2]; b[np * 2 + 1][1] = r[3];
        }
    }
}

template<int BM, int STAGES, bool TRANSB, bool BIAS, bool GELU, bool SPLITOUT, bool RESID>
__global__ void __launch_bounds__(256, 2) gemm_bf3(
    int M, int N, int K,
    const __nv_bfloat16* __restrict__ Ah, const __nv_bfloat16* __restrict__ Al,
    const __nv_bfloat16* __restrict__ Bh, const __nv_bfloat16* __restrict__ Bl,
    const float* __restrict__ bias, float* __restrict__ C,
    __nv_bfloat16* __restrict__ Oh, __nv_bfloat16* __restrict__ Ol)
{
    using CF = GC<BM, STAGES, TRANSB>;
    constexpr int MT = BM / 32;            // m16 tiles per warp (4 or 2)
    extern __shared__ __nv_bfloat16 sm[];
    const int tid  = threadIdx.x;
    const int lane = tid & 31;
    const int warp = tid >> 5;
    const int crow = blockIdx.y * BM;
    const int ccol = blockIdx.x * BN;
    const int warpM = (warp >> 2) * (BM / 2);
    const int warpN = (warp & 3) * 32;
    const int r = lane >> 2, c = lane & 3;

    float acc[MT][4][4];
    #pragma unroll
    for (int mt = 0; mt < MT; mt++)
        #pragma unroll
        for (int nt = 0; nt < 4; nt++)
            #pragma unroll
            for (int i = 0; i < 4; i++) acc[mt][nt][i] = 0.f;

    const int KT = K / BK;

    auto compute_stage = [&](int st) {
        const __nv_bfloat16* base = sm + st * CF::SE;
        const __nv_bfloat16* As_h = base;
        const __nv_bfloat16* As_l = base + CF::AE;
        const __nv_bfloat16* Bs_h = base + 2 * CF::AE;
        const __nv_bfloat16* Bs_l = base + 2 * CF::AE + CF::BE;
        #pragma unroll
        for (int ks = 0; ks < 2; ks++) {
            const int kk = ks * 16;
            uint32_t ah[MT][4], al[MT][4], bh[4][2], bl[4][2];
            load_afrag<MT>(ah, As_h, warpM, lane, kk);
            load_bfrag<TRANSB>(bh, Bs_h, warpN, lane, kk);
            #pragma unroll
            for (int mt = 0; mt < MT; mt++)
                #pragma unroll
                for (int nt = 0; nt < 4; nt++)
                    MMA_BF16(acc[mt][nt], ah[mt], bh[nt]);
            load_afrag<MT>(al, As_l, warpM, lane, kk);
            #pragma unroll
            for (int mt = 0; mt < MT; mt++)
                #pragma unroll
                for (int nt = 0; nt < 4; nt++)
                    MMA_BF16(acc[mt][nt], al[mt], bh[nt]);
            load_bfrag<TRANSB>(bl, Bs_l, warpN, lane, kk);
            #pragma unroll
            for (int mt = 0; mt < MT; mt++)
                #pragma unroll
                for (int nt = 0; nt < 4; nt++)
                    MMA_BF16(acc[mt][nt], ah[mt], bl[nt]);
        }
    };

    if constexpr (STAGES == 3) {
        load_stage<BM, STAGES, TRANSB>(sm, 0, 0, Ah, Al, Bh, Bl, N, K, crow, ccol, tid);
        asm volatile("cp.async.commit_group;" ::: "memory");
        load_stage<BM, STAGES, TRANSB>(sm, 1, BK, Ah, Al, Bh, Bl, N, K, crow, ccol, tid);
        asm volatile("cp.async.commit_group;" ::: "memory");
        for (int kt = 0; kt < KT; kt++) {
            asm volatile("cp.async.wait_group 1;" ::: "memory");
            __syncthreads();
            if (kt + 2 < KT)
                load_stage<BM, STAGES, TRANSB>(sm, (kt + 2) % 3, (kt + 2) * BK,
                                               Ah, Al, Bh, Bl, N, K, crow, ccol, tid);
            asm volatile("cp.async.commit_group;" ::: "memory");  // maybe empty
            compute_stage(kt % 3);
        }
    } else {
        load_stage<BM, STAGES, TRANSB>(sm, 0, 0, Ah, Al, Bh, Bl, N, K, crow, ccol, tid);
        asm volatile("cp.async.commit_group;" ::: "memory");
        for (int kt = 0; kt < KT; kt++) {
            if (kt + 1 < KT) {
                load_stage<BM, STAGES, TRANSB>(sm, (kt + 1) & 1, (kt + 1) * BK,
                                               Ah, Al, Bh, Bl, N, K, crow, ccol, tid);
                asm volatile("cp.async.commit_group;" ::: "memory");
                asm volatile("cp.async.wait_group 1;" ::: "memory");
            } else {
                asm volatile("cp.async.wait_group 0;" ::: "memory");
            }
            __syncthreads();
            compute_stage(kt & 1);
            __syncthreads();
        }
    }

    // ---- epilogue ----
    #pragma unroll
    for (int mt = 0; mt < MT; mt++) {
        #pragma unroll
        for (int nt = 0; nt < 4; nt++) {
            int m0 = crow + warpM + mt * 16;
            int n0 = ccol + warpN + nt * 8;
            #pragma unroll
            for (int half = 0; half < 2; half++) {
                int m = m0 + r + half * 8;
                int n = n0 + c * 2;
                if (n >= N) continue;
                float v0 = acc[mt][nt][half * 2 + 0];
                float v1 = acc[mt][nt][half * 2 + 1];
                if (BIAS) { v0 += bias[n]; v1 += bias[n + 1]; }
                if (GELU) { v0 = gelu_exact(v0); v1 = gelu_exact(v1); }
                if (RESID) {
                    float2 o = *reinterpret_cast<float2*>(C + (size_t)m * N + n);
                    v0 += o.x; v1 += o.y;
                }
                if (SPLITOUT) {
                    __nv_bfloat16 h0, l0, h1, l1;
                    split2(v0, h0, l0); split2(v1, h1, l1);
                    *reinterpret_cast<__nv_bfloat162*>(Oh + (size_t)m * N + n) =
                        __nv_bfloat162{h0, h1};
                    *reinterpret_cast<__nv_bfloat162*>(Ol + (size_t)m * N + n) =
                        __nv_bfloat162{l0, l1};
                } else {
                    *reinterpret_cast<float2*>(C + (size_t)m * N + n) =
                        make_float2(v0, v1);
                }
            }
        }
    }
}

constexpr int SM_NT128 = GC<128, 3, false>::SMEM;   // 113664
constexpr int SM_NT64  = GC<64,  3, false>::SMEM;   //  82944
constexpr int SM_TR    = GC<128, 2, true >::SMEM;   //  81920

// ---------------- launch ----------------
extern "C" void kernel_launch(void* const* d_in, const int* in_sizes, int n_in,
                              void* d_out, int out_size) {
    const int*   node_idx  = (const int*)  d_in[0];
    const int*   edge_idx  = (const int*)  d_in[1];
    const float* edge_w    = (const float*)d_in[2];
    const float* frozen    = (const float*)d_in[3];
    const float* W_root    = (const float*)d_in[4];
    const float* W_nbr     = (const float*)d_in[5];
    const float* b_mp      = (const float*)d_in[6];
    const float* W_post    = (const float*)d_in[7];
    const float* b_post    = (const float*)d_in[8];
    const float* fallback  = (const float*)d_in[9];
    const float* W_in      = (const float*)d_in[10];
    const float* b_in      = (const float*)d_in[11];
    const float* ln_g      = (const float*)d_in[12];
    const float* ln_b      = (const float*)d_in[13];
    const float* W1        = (const float*)d_in[14];
    const float* b1        = (const float*)d_in[15];
    const float* W2        = (const float*)d_in[16];
    const float* W_bil     = (const float*)d_in[17];
    const float* out_emb   = (const float*)d_in[18];
    float*       logits    = (float*)d_out;

    float *p_h;
    cudaGetSymbolAddress((void**)&p_h, g_h);
    __nv_bfloat16 *p_perth, *p_pertl, *p_xnh, *p_xnl, *p_acth, *p_actl;
    __nv_bfloat16 *p_hsh, *p_hsl, *p_projh, *p_projl;
    __nv_bfloat16 *p_Winh, *p_Winl, *p_W1h, *p_W1l, *p_W2h, *p_W2l;
    __nv_bfloat16 *p_bilh, *p_bill, *p_oeh, *p_oel;
    cudaGetSymbolAddress((void**)&p_perth, g_perth);
    cudaGetSymbolAddress((void**)&p_pertl, g_pertl);
    cudaGetSymbolAddress((void**)&p_xnh,  g_xnh);
    cudaGetSymbolAddress((void**)&p_xnl,  g_xnl);
    cudaGetSymbolAddress((void**)&p_acth, g_acth);
    cudaGetSymbolAddress((void**)&p_actl, g_actl);
    cudaGetSymbolAddress((void**)&p_hsh,  g_hsh);
    cudaGetSymbolAddress((void**)&p_hsl,  g_hsl);
    cudaGetSymbolAddress((void**)&p_projh, g_projh);
    cudaGetSymbolAddress((void**)&p_projl, g_projl);
    cudaGetSymbolAddress((void**)&p_Winh, g_Winh);
    cudaGetSymbolAddress((void**)&p_Winl, g_Winl);
    cudaGetSymbolAddress((void**)&p_W1h,  g_W1h);
    cudaGetSymbolAddress((void**)&p_W1l,  g_W1l);
    cudaGetSymbolAddress((void**)&p_W2h,  g_W2h);
    cudaGetSymbolAddress((void**)&p_W2l,  g_W2l);
    cudaGetSymbolAddress((void**)&p_bilh, g_bilh);
    cudaGetSymbolAddress((void**)&p_bill, g_bill);
    cudaGetSymbolAddress((void**)&p_oeh,  g_oeh);
    cudaGetSymbolAddress((void**)&p_oel,  g_oel);

    cudaFuncSetAttribute(gemm_bf3<64,  3, false, true,  true,  false, false>,
        cudaFuncAttributeMaxDynamicSharedMemorySize, SM_NT64);
    cudaFuncSetAttribute(gemm_bf3<128, 3, false, true,  true,  true,  false>,
        cudaFuncAttributeMaxDynamicSharedMemorySize, SM_NT128);
    cudaFuncSetAttribute(gemm_bf3<64,  3, false, false, false, false, true>,
        cudaFuncAttributeMaxDynamicSharedMemorySize, SM_NT64);
    cudaFuncSetAttribute(gemm_bf3<64,  3, false, false, false, true,  true>,
        cudaFuncAttributeMaxDynamicSharedMemorySize, SM_NT64);
    cudaFuncSetAttribute(gemm_bf3<128, 3, false, false, false, true,  false>,
        cudaFuncAttributeMaxDynamicSharedMemorySize, SM_NT128);
    cudaFuncSetAttribute(gemm_bf3<128, 2, true,  false, false, false, false>,
        cudaFuncAttributeMaxDynamicSharedMemorySize, SM_TR);

    // --- graph phase (edge at launch index 3 for ncu) ---
    zero_kernel<<<512, 256>>>();                               // 0
    mark_kernel<<<(BATCH + 255) / 256, 256>>>(node_idx);       // 1
    fused_wc_kernel<<<GNN_DIM + 1 + 128, GNN_DIM>>>(           // 2
        W_root, W_nbr, W_post, b_mp, b_post, W_in);
    {
        int warps = (N_EDGES + 31) / 32;
        int blocks = (warps + 7) / 8;
        edge_kernel<<<blocks, 256>>>(edge_idx, edge_w, frozen);  // 3
    }
    pert_kernel<<<BATCH / 8, GNN_DIM>>>(node_idx, frozen, fallback);  // 4

    // h = gelu(pert @ W_in + b_in)   [BM=64 tile: 4x32 = 128 CTAs]
    {
        dim3 grid(HEAD_DIM / BN, BATCH / 64);
        gemm_bf3<64, 3, false, true, true, false, false><<<grid, 256, SM_NT64>>>(
            BATCH, HEAD_DIM, GNN_DIM, p_perth, p_pertl, p_Winh, p_Winl,
            b_in, p_h, nullptr, nullptr);
    }

    // remaining weight splits
    split_kernel<<<2048, 256>>>(W1,    p_W1h,  p_W1l,  N_RES * HEAD_DIM * FF_DIM / 4);
    split_kernel<<<2048, 256>>>(W2,    p_W2h,  p_W2l,  N_RES * FF_DIM * HEAD_DIM / 4);
    split_kernel<<<512, 256>>>(W_bil,  p_bilh, p_bill, HEAD_DIM * BIL_DIM / 4);
    split_kernel<<<1024, 256>>>(out_emb, p_oeh, p_oel, N_GENES * HEAD_DIM / 4);

    for (int i = 0; i < N_RES; i++) {
        ln_kernel<<<BATCH, 128>>>(p_h, ln_g + (size_t)i * HEAD_DIM,
                                  ln_b + (size_t)i * HEAD_DIM);
        // W1: N=2048 -> 16x16 = 256 CTAs at BM=128 (fine)
        dim3 g1(FF_DIM / BN, BATCH / 128);
        gemm_bf3<128, 3, false, true, true, true, false><<<g1, 256, SM_NT128>>>(
            BATCH, FF_DIM, HEAD_DIM, p_xnh, p_xnl,
            p_W1h + (size_t)i * HEAD_DIM * FF_DIM, p_W1l + (size_t)i * HEAD_DIM * FF_DIM,
            b1 + (size_t)i * FF_DIM, nullptr, p_acth, p_actl);
        // W2: N=512 -> BM=64 tile: 4x32 = 128 CTAs (was 64)
        dim3 g2(HEAD_DIM / BN, BATCH / 64);
        if (i < N_RES - 1) {
            gemm_bf3<64, 3, false, false, false, false, true><<<g2, 256, SM_NT64>>>(
                BATCH, HEAD_DIM, FF_DIM, p_acth, p_actl,
                p_W2h + (size_t)i * FF_DIM * HEAD_DIM, p_W2l + (size_t)i * FF_DIM * HEAD_DIM,
                nullptr, p_h, nullptr, nullptr);
        } else {
            gemm_bf3<64, 3, false, false, false, true, true><<<g2, 256, SM_NT64>>>(
                BATCH, HEAD_DIM, FF_DIM, p_acth, p_actl,
                p_W2h + (size_t)i * FF_DIM * HEAD_DIM, p_W2l + (size_t)i * FF_DIM * HEAD_DIM,
                nullptr, p_h, p_hsh, p_hsl);
        }
    }
    // proj = h @ W_bil (split output): 12x16 = 192 CTAs at BM=128
    {
        dim3 grid(BIL_DIM / BN, BATCH / 128);
        gemm_bf3<128, 3, false, false, false, true, false><<<grid, 256, SM_NT128>>>(
            BATCH, BIL_DIM, HEAD_DIM, p_hsh, p_hsl, p_bilh, p_bill,
            nullptr, nullptr, p_projh, p_projl);
    }
    // logits = reshape(proj,[B*3,512]) @ out_emb^T: 52x48 CTAs
    {
        dim3 grid((N_GENES + BN - 1) / BN, (BATCH * N_CLASSES) / 128);
        gemm_bf3<128, 2, true, false, false, false, false><<<grid, 256, SM_TR>>>(
            BATCH * N_CLASSES, N_GENES, HEAD_DIM, p_projh, p_projl, p_oeh, p_oel,
            nullptr, logits, nullptr, nullptr);
    }
}

// round 14
// speedup vs baseline: 1.6960x; 1.0134x over previous
#include <cuda_runtime.h>
#include <cuda_bf16.h>
#include <math.h>
#include <stdint.h>

// ---------------- problem constants ----------------
#define N_NODES   19385
#define N_EDGES   1200000
#define GNN_DIM   256
#define HEAD_DIM  512
#define EXPAND    4
#define N_CLASSES 3
#define N_GENES   6640
#define N_RES     6
#define BATCH     2048
#define FF_DIM    (HEAD_DIM * EXPAND)    // 2048
#define BIL_DIM   (N_CLASSES * HEAD_DIM) // 1536
#define OE_PAD    6656                   // N_GENES padded to 32/128 multiple

// ---------------- fp32 scratch ----------------
__device__ float g_aggrc[(size_t)BATCH * GNN_DIM];
__device__ int   g_slot[N_NODES];
__device__ float g_Wc1[GNN_DIM * GNN_DIM];
__device__ float g_Wc2[GNN_DIM * GNN_DIM];
__device__ float g_bc[GNN_DIM];
__device__ float g_h[(size_t)BATCH * HEAD_DIM];

// ---------------- bf16 split scratch (hi/lo pairs) ----------------
__device__ __nv_bfloat16 g_perth[(size_t)BATCH * GNN_DIM];
__device__ __nv_bfloat16 g_pertl[(size_t)BATCH * GNN_DIM];
__device__ __nv_bfloat16 g_xnh[(size_t)BATCH * HEAD_DIM];
__device__ __nv_bfloat16 g_xnl[(size_t)BATCH * HEAD_DIM];
__device__ __nv_bfloat16 g_acth[(size_t)BATCH * FF_DIM];
__device__ __nv_bfloat16 g_actl[(size_t)BATCH * FF_DIM];
__device__ __nv_bfloat16 g_hsh[(size_t)BATCH * HEAD_DIM];
__device__ __nv_bfloat16 g_hsl[(size_t)BATCH * HEAD_DIM];
__device__ __nv_bfloat16 g_projh[(size_t)BATCH * BIL_DIM];
__device__ __nv_bfloat16 g_projl[(size_t)BATCH * BIL_DIM];
// weight splits ([K,N] layout); out_emb transposed to [HEAD_DIM, OE_PAD]
__device__ __nv_bfloat16 g_Winh[GNN_DIM * HEAD_DIM];
__device__ __nv_bfloat16 g_Winl[GNN_DIM * HEAD_DIM];
__device__ __nv_bfloat16 g_W1h[(size_t)N_RES * HEAD_DIM * FF_DIM];
__device__ __nv_bfloat16 g_W1l[(size_t)N_RES * HEAD_DIM * FF_DIM];
__device__ __nv_bfloat16 g_W2h[(size_t)N_RES * FF_DIM * HEAD_DIM];
__device__ __nv_bfloat16 g_W2l[(size_t)N_RES * FF_DIM * HEAD_DIM];
__device__ __nv_bfloat16 g_bilh[HEAD_DIM * BIL_DIM];
__device__ __nv_bfloat16 g_bill[HEAD_DIM * BIL_DIM];
__device__ __nv_bfloat16 g_oeh[(size_t)HEAD_DIM * OE_PAD];
__device__ __nv_bfloat16 g_oel[(size_t)HEAD_DIM * OE_PAD];

// ---------------- helpers ----------------
__device__ __forceinline__ float gelu_exact(float v) {
    return 0.5f * v * (1.0f + erff(v * 0.70710678118654752f));
}
__device__ __forceinline__ void split2(float x, __nv_bfloat16& h, __nv_bfloat16& l) {
    h = __float2bfloat16_rn(x);
    l = __float2bfloat16_rn(x - __bfloat162float(h));
}
__device__ __forceinline__ uint32_t smem_u32(const void* p) {
    return (uint32_t)__cvta_generic_to_shared(p);
}
__device__ __forceinline__ void cp16(uint32_t dst, const void* src, bool pred) {
    int sz = pred ? 16 : 0;
    asm volatile("cp.async.cg.shared.global [%0], [%1], 16, %2;\n"
                 :: "r"(dst), "l"(src), "r"(sz));
}
__device__ __forceinline__ void ldm_x4(uint32_t* r, uint32_t addr) {
    asm volatile("ldmatrix.sync.aligned.m8n8.x4.shared.b16 {%0,%1,%2,%3}, [%4];"
                 : "=r"(r[0]), "=r"(r[1]), "=r"(r[2]), "=r"(r[3]) : "r"(addr));
}
__device__ __forceinline__ void ldm_x4_t(uint32_t* r, uint32_t addr) {
    asm volatile("ldmatrix.sync.aligned.m8n8.x4.trans.shared.b16 {%0,%1,%2,%3}, [%4];"
                 : "=r"(r[0]), "=r"(r[1]), "=r"(r[2]), "=r"(r[3]) : "r"(addr));
}
#define MMA_BF16(D, A, B)                                                   \
    asm volatile(                                                           \
        "mma.sync.aligned.m16n8k16.row.col.f32.bf16.bf16.f32 "              \
        "{%0,%1,%2,%3},{%4,%5,%6,%7},{%8,%9},{%0,%1,%2,%3};"                \
        : "+f"((D)[0]), "+f"((D)[1]), "+f"((D)[2]), "+f"((D)[3])            \
        : "r"((A)[0]), "r"((A)[1]), "r"((A)[2]), "r"((A)[3]),               \
          "r"((B)[0]), "r"((B)[1]))

// ---------------- zero compact scratch + slot init ----------------
__global__ void zero_kernel() {
    int stride = gridDim.x * blockDim.x;
    int tid = blockIdx.x * blockDim.x + threadIdx.x;
    int total4 = BATCH * (GNN_DIM / 4);
    float4* a4 = reinterpret_cast<float4*>(g_aggrc);
    for (int i = tid; i < total4; i += stride)
        a4[i] = make_float4(0.f, 0.f, 0.f, 0.f);
    for (int i = tid; i < N_NODES; i += stride)
        g_slot[i] = -1;
}

__global__ void mark_kernel(const int* __restrict__ idx) {
    int b = blockIdx.x * blockDim.x + threadIdx.x;
    if (b < BATCH) {
        int n = idx[b];
        if (n >= 0) atomicCAS(&g_slot[n], -1, b);
    }
}

// ---------------- filtered edge scatter-add into compact buffer ----------------
__global__ void edge_kernel(const int* __restrict__ ei, const float* __restrict__ ew,
                            const float* __restrict__ x0) {
    const int lane = threadIdx.x & 31;
    const int warp = (blockIdx.x * blockDim.x + threadIdx.x) >> 5;
    const int e0 = warp * 32;
    if (e0 >= N_EDGES) return;
    const int e = e0 + lane;
    int sl = -1, s = 0; float w = 0.f;
    if (e < N_EDGES) {
        int d = ei[N_EDGES + e];
        sl = g_slot[d];
        if (sl >= 0) { s = ei[e]; w = ew[e]; }
    }
    unsigned mask = __ballot_sync(0xffffffffu, sl >= 0);
    while (mask) {
        int b = __ffs(mask) - 1; mask &= (mask - 1);
        int   ss = __shfl_sync(0xffffffffu, s, b);
        int   dd = __shfl_sync(0xffffffffu, sl, b);
        float ww = __shfl_sync(0xffffffffu, w, b);
        const float4* xr = reinterpret_cast<const float4*>(x0 + (size_t)ss * GNN_DIM);
        float* ar = g_aggrc + (size_t)dd * GNN_DIM;
        #pragma unroll
        for (int i = 0; i < 2; i++) {
            int c = lane + i * 32;
            float4 v = xr[c];
            asm volatile("red.global.add.v4.f32 [%0], {%1,%2,%3,%4};"
                         :: "l"(ar + c * 4), "f"(v.x * ww), "f"(v.y * ww),
                            "f"(v.z * ww), "f"(v.w * ww) : "memory");
        }
    }
}

// ---------------- fused: fold weights + bc + W_in split ----------------
__global__ void fused_wc_kernel(const float* __restrict__ Wr, const float* __restrict__ Wn,
                                const float* __restrict__ Wp,
                                const float* __restrict__ bmp, const float* __restrict__ bpost,
                                const float* __restrict__ Win) {
    int bx = blockIdx.x, j = threadIdx.x;
    if (bx < GNN_DIM) {
        __shared__ float r[GNN_DIM], nn[GNN_DIM];
        r[j]  = Wr[bx * GNN_DIM + j] + (bx == j ? 1.f : 0.f);
        nn[j] = Wn[bx * GNN_DIM + j];
        __syncthreads();
        float a1[4] = {0, 0, 0, 0}, a2[4] = {0, 0, 0, 0};
        #pragma unroll 2
        for (int k = 0; k < GNN_DIM; k += 4) {
            #pragma unroll
            for (int u = 0; u < 4; u++) {
                float wp = Wp[(k + u) * GNN_DIM + j];
                a1[u] += r[k + u] * wp;
                a2[u] += nn[k + u] * wp;
            }
        }
        g_Wc1[bx * GNN_DIM + j] = (a1[0] + a1[1]) + (a1[2] + a1[3]);
        g_Wc2[bx * GNN_DIM + j] = (a2[0] + a2[1]) + (a2[2] + a2[3]);
    } else if (bx == GNN_DIM) {
        float a[4] = {bpost[j], 0, 0, 0};
        #pragma unroll 2
        for (int k = 0; k < GNN_DIM; k += 4) {
            #pragma unroll
            for (int u = 0; u < 4; u++)
                a[u] += bmp[k + u] * Wp[(k + u) * GNN_DIM + j];
        }
        g_bc[j] = (a[0] + a[1]) + (a[2] + a[3]);
    } else {
        int i = (bx - GNN_DIM - 1) * 256 + j;
        float4 v = reinterpret_cast<const float4*>(Win)[i];
        __nv_bfloat16 h0, l0, h1, l1, h2, l2, h3, l3;
        split2(v.x, h0, l0); split2(v.y, h1, l1);
        split2(v.z, h2, l2); split2(v.w, h3, l3);
        __nv_bfloat162* ph = reinterpret_cast<__nv_bfloat162*>(g_Winh) + i * 2;
        __nv_bfloat162* pl = reinterpret_cast<__nv_bfloat162*>(g_Winl) + i * 2;
        ph[0] = __nv_bfloat162{h0, h1}; ph[1] = __nv_bfloat162{h2, h3};
        pl[0] = __nv_bfloat162{l0, l1}; pl[1] = __nv_bfloat162{l2, l3};
    }
}

// ---------------- per-batch-row node transform -> split pert ----------------
__global__ void pert_kernel(const int* __restrict__ idx, const float* __restrict__ x0,
                            const float* __restrict__ fb) {
    constexpr int RPB = 8;
    __shared__ float xr[RPB][GNN_DIM];
    __shared__ float ar[RPB][GNN_DIM];
    __shared__ int   ns[RPB], sl[RPB];
    int j = threadIdx.x;
    int b0 = blockIdx.x * RPB;
    if (j < RPB) {
        int n = idx[b0 + j];
        ns[j] = n;
        sl[j] = (n >= 0) ? g_slot[n] : 0;
    }
    __syncthreads();
    #pragma unroll
    for (int r = 0; r < RPB; r++) {
        int n = ns[r]; int sn = (n < 0) ? 0 : n;
        xr[r][j] = x0[(size_t)sn * GNN_DIM + j];
        ar[r][j] = g_aggrc[(size_t)sl[r] * GNN_DIM + j];
    }
    __syncthreads();
    float acc[RPB];
    #pragma unroll
    for (int r = 0; r < RPB; r++) acc[r] = g_bc[j];
    for (int k = 0; k < GNN_DIM; k++) {
        float w1 = g_Wc1[k * GNN_DIM + j];
        float w2 = g_Wc2[k * GNN_DIM + j];
        #pragma unroll
        for (int r = 0; r < RPB; r++)
            acc[r] += xr[r][k] * w1 + ar[r][k] * w2;
    }
    float fbj = fb[j];
    #pragma unroll
    for (int r = 0; r < RPB; r++) {
        float v = (ns[r] >= 0) ? acc[r] : fbj;
        __nv_bfloat16 h, l; split2(v, h, l);
        g_perth[(size_t)(b0 + r) * GNN_DIM + j] = h;
        g_pertl[(size_t)(b0 + r) * GNN_DIM + j] = l;
    }
}

// ---------------- layernorm -> split xn ----------------
__global__ void ln_kernel(const float* __restrict__ hbuf, const float* __restrict__ g,
                          const float* __restrict__ bb) {
    int row = blockIdx.x;
    const float* x = hbuf + (size_t)row * HEAD_DIM;
    int tid = threadIdx.x;   // 128
    float v[4]; float s = 0.f, s2 = 0.f;
    #pragma unroll
    for (int i = 0; i < 4; i++) {
        v[i] = x[tid + i * 128];
        s += v[i]; s2 += v[i] * v[i];
    }
    #pragma unroll
    for (int o = 16; o; o >>= 1) {
        s  += __shfl_down_sync(0xffffffffu, s, o);
        s2 += __shfl_down_sync(0xffffffffu, s2, o);
    }
    __shared__ float ss[4], ss2[4];
    if ((tid & 31) == 0) { ss[tid >> 5] = s; ss2[tid >> 5] = s2; }
    __syncthreads();
    s  = ss[0] + ss[1] + ss[2] + ss[3];
    s2 = ss2[0] + ss2[1] + ss2[2] + ss2[3];
    float mu  = s * (1.f / HEAD_DIM);
    float var = s2 * (1.f / HEAD_DIM) - mu * mu;
    float rs  = rsqrtf(var + 1e-5f);
    #pragma unroll
    for (int i = 0; i < 4; i++) {
        int j = tid + i * 128;
        float o = (v[i] - mu) * rs * g[j] + bb[j];
        __nv_bfloat16 hh, ll; split2(o, hh, ll);
        g_xnh[(size_t)row * HEAD_DIM + j] = hh;
        g_xnl[(size_t)row * HEAD_DIM + j] = ll;
    }
}

// ---------------- fp32 -> bf16 hi/lo split (weights) ----------------
__global__ void split_kernel(const float* __restrict__ src,
                             __nv_bfloat16* __restrict__ dh,
                             __nv_bfloat16* __restrict__ dl, int n4) {
    int stride = gridDim.x * blockDim.x;
    for (int i = blockIdx.x * blockDim.x + threadIdx.x; i < n4; i += stride) {
        float4 v = reinterpret_cast<const float4*>(src)[i];
        __nv_bfloat16 h0, l0, h1, l1, h2, l2, h3, l3;
        split2(v.x, h0, l0); split2(v.y, h1, l1);
        split2(v.z, h2, l2); split2(v.w, h3, l3);
        __nv_bfloat162* ph = reinterpret_cast<__nv_bfloat162*>(dh) + i * 2;
        __nv_bfloat162* pl = reinterpret_cast<__nv_bfloat162*>(dl) + i * 2;
        ph[0] = __nv_bfloat162{h0, h1}; ph[1] = __nv_bfloat162{h2, h3};
        pl[0] = __nv_bfloat162{l0, l1}; pl[1] = __nv_bfloat162{l2, l3};
    }
}

// ---------------- out_emb [N_GENES, 512] -> transposed padded split ---------
// oeT[k][n] (n padded to OE_PAD with zeros). blockDim (32,8), grid (208, 16).
__global__ void tsplit_oe(const float* __restrict__ src,
                          __nv_bfloat16* __restrict__ dh,
                          __nv_bfloat16* __restrict__ dl) {
    __shared__ float t[32][33];
    int n0 = blockIdx.x * 32, k0 = blockIdx.y * 32;
    int tx = threadIdx.x, ty = threadIdx.y;
    #pragma unroll
    for (int i = 0; i < 4; i++) {
        int n = n0 + ty + i * 8;
        t[ty + i * 8][tx] = (n < N_GENES) ? src[(size_t)n * HEAD_DIM + k0 + tx] : 0.f;
    }
    __syncthreads();
    #pragma unroll
    for (int i = 0; i < 4; i++) {
        int kl = ty + i * 8;
        float v = t[tx][kl];
        __nv_bfloat16 h, l; split2(v, h, l);
        size_t o = (size_t)(k0 + kl) * OE_PAD + n0 + tx;
        dh[o] = h; dl[o] = l;
    }
}

// ================= bf16x3 tensor-core GEMM (BMx128x32, occ2, ring pipeline) ==
constexpr int BN = 128, BK = 32;
constexpr int ASTR = BK + 8;        // 40
constexpr int BSTR = BN + 8;        // 136

template<int BM, int STAGES>
struct GC {
    static constexpr int AE = BM * ASTR;
    static constexpr int BE = 32 * BSTR;     // 4352
    static constexpr int SE = 2 * AE + 2 * BE;
    static constexpr int SMEM = STAGES * SE * 2;
};
// BM=128 x3: 113664 B (occ2 <=116736)  |  BM=64 x4: 110592 B (occ2)

template<int BM, int STAGES>
__device__ __forceinline__ void load_stage(
    __nv_bfloat16* sm, int stage, int k0,
    const __nv_bfloat16* Ah, const __nv_bfloat16* Al,
    const __nv_bfloat16* Bh, const __nv_bfloat16* Bl,
    int ldb, int K, int crow, int ccol, int tid)
{
    using C = GC<BM, STAGES>;
    __nv_bfloat16* base = sm + stage * C::SE;
    __nv_bfloat16* As_h = base;
    __nv_bfloat16* As_l = base + C::AE;
    __nv_bfloat16* Bs_h = base + 2 * C::AE;
    __nv_bfloat16* Bs_l = base + 2 * C::AE + C::BE;
    #pragma unroll
    for (int i = 0; i < BM / 64; i++) {
        int q = tid + i * 256;
        int row = q >> 2, c8 = (q & 3) * 8;
        size_t goff = (size_t)(crow + row) * K + k0 + c8;
        uint32_t soff = row * ASTR + c8;
        cp16(smem_u32(As_h + soff), Ah + goff, true);
        cp16(smem_u32(As_l + soff), Al + goff, true);
    }
    #pragma unroll
    for (int i = 0; i < 2; i++) {
        int q = tid + i * 256;
        int row = q >> 4, c8 = (q & 15) * 8;
        size_t goff = (size_t)(k0 + row) * ldb + ccol + c8;
        uint32_t soff = row * BSTR + c8;
        cp16(smem_u32(Bs_h + soff), Bh + goff, true);
        cp16(smem_u32(Bs_l + soff), Bl + goff, true);
    }
}

template<int MT>
__device__ __forceinline__ void load_afrag(uint32_t a[MT][4], const __nv_bfloat16* As,
                                           int warpM, int lane, int kk) {
    int lrow = warpM + (lane & 15);
    int lcol = kk + ((lane >> 4) << 3);
    #pragma unroll
    for (int mt = 0; mt < MT; mt++)
        ldm_x4(a[mt], smem_u32(As + (lrow + mt * 16) * ASTR + lcol));
}

__device__ __forceinline__ void load_bfrag(uint32_t b[4][2], const __nv_bfloat16* Bs,
                                           int warpN, int lane, int kk) {
    int j = lane >> 3, r8 = lane & 7;
    int krow = kk + r8 + ((j & 1) << 3);
    #pragma unroll
    for (int np = 0; np < 2; np++) {
        int ncol = warpN + np * 16 + ((j >> 1) << 3);
        uint32_t r[4];
        ldm_x4_t(r, smem_u32(Bs + krow * BSTR + ncol));
        b[np * 2][0] = r[0]; b[np * 2][1] = r[1];
        b[np * 2 + 1][0] = r[2]; b[np * 2 + 1][1] = r[3];
    }
}

template<int BM, int STAGES, bool BIAS, bool GELU, bool SPLITOUT, bool RESID>
__global__ void __launch_bounds__(256, 2) gemm_bf3(
    int M, int N, int ldb, int K,
    const __nv_bfloat16* __restrict__ Ah, const __nv_bfloat16* __restrict__ Al,
    const __nv_bfloat16* __restrict__ Bh, const __nv_bfloat16* __restrict__ Bl,
    const float* __restrict__ bias, float* __restrict__ C,
    __nv_bfloat16* __restrict__ Oh, __nv_bfloat16* __restrict__ Ol)
{
    using CF = GC<BM, STAGES>;
    constexpr int MT = BM / 32;
    extern __shared__ __nv_bfloat16 sm[];
    const int tid  = threadIdx.x;
    const int lane = tid & 31;
    const int warp = tid >> 5;
    const int crow = blockIdx.y * BM;
    const int ccol = blockIdx.x * BN;
    const int warpM = (warp >> 2) * (BM / 2);
    const int warpN = (warp & 3) * 32;
    const int r = lane >> 2, c = lane & 3;

    float acc[MT][4][4];
    #pragma unroll
    for (int mt = 0; mt < MT; mt++)
        #pragma unroll
        for (int nt = 0; nt < 4; nt++)
            #pragma unroll
            for (int i = 0; i < 4; i++) acc[mt][nt][i] = 0.f;

    const int KT = K / BK;

    auto compute_stage = [&](int st) {
        const __nv_bfloat16* base = sm + st * CF::SE;
        const __nv_bfloat16* As_h = base;
        const __nv_bfloat16* As_l = base + CF::AE;
        const __nv_bfloat16* Bs_h = base + 2 * CF::AE;
        const __nv_bfloat16* Bs_l = base + 2 * CF::AE + CF::BE;
        #pragma unroll
        for (int ks = 0; ks < 2; ks++) {
            const int kk = ks * 16;
            uint32_t ah[MT][4], al[MT][4], bh[4][2], bl[4][2];
            load_afrag<MT>(ah, As_h, warpM, lane, kk);
            load_bfrag(bh, Bs_h, warpN, lane, kk);
            #pragma unroll
            for (int mt = 0; mt < MT; mt++)
                #pragma unroll
                for (int nt = 0; nt < 4; nt++)
                    MMA_BF16(acc[mt][nt], ah[mt], bh[nt]);
            load_afrag<MT>(al, As_l, warpM, lane, kk);
            #pragma unroll
            for (int mt = 0; mt < MT; mt++)
                #pragma unroll
                for (int nt = 0; nt < 4; nt++)
                    MMA_BF16(acc[mt][nt], al[mt], bh[nt]);
            load_bfrag(bl, Bs_l, warpN, lane, kk);
            #pragma unroll
            for (int mt = 0; mt < MT; mt++)
                #pragma unroll
                for (int nt = 0; nt < 4; nt++)
                    MMA_BF16(acc[mt][nt], ah[mt], bl[nt]);
        }
    };

    // ring pipeline: prologue STAGES-1 loads; per iter: wait oldest, sync,
    // issue next load (maybe-empty commit), compute current stage.
    #pragma unroll
    for (int s = 0; s < STAGES - 1; s++) {
        load_stage<BM, STAGES>(sm, s, s * BK, Ah, Al, Bh, Bl, ldb, K, crow, ccol, tid);
        asm volatile("cp.async.commit_group;" ::: "memory");
    }
    for (int kt = 0; kt < KT; kt++) {
        asm volatile("cp.async.wait_group %0;" :: "n"(STAGES - 2) : "memory");
        __syncthreads();
        if (kt + STAGES - 1 < KT)
            load_stage<BM, STAGES>(sm, (kt + STAGES - 1) % STAGES,
                                   (kt + STAGES - 1) * BK,
                                   Ah, Al, Bh, Bl, ldb, K, crow, ccol, tid);
        asm volatile("cp.async.commit_group;" ::: "memory");
        compute_stage(kt % STAGES);
    }

    // ---- epilogue ----
    #pragma unroll
    for (int mt = 0; mt < MT; mt++) {
        #pragma unroll
        for (int nt = 0; nt < 4; nt++) {
            int m0 = crow + warpM + mt * 16;
            int n0 = ccol + warpN + nt * 8;
            #pragma unroll
            for (int half = 0; half < 2; half++) {
                int m = m0 + r + half * 8;
                int n = n0 + c * 2;
                if (n >= N) continue;
                float v0 = acc[mt][nt][half * 2 + 0];
                float v1 = acc[mt][nt][half * 2 + 1];
                if (BIAS) { v0 += bias[n]; v1 += bias[n + 1]; }
                if (GELU) { v0 = gelu_exact(v0); v1 = gelu_exact(v1); }
                if (RESID) {
                    float2 o = *reinterpret_cast<float2*>(C + (size_t)m * N + n);
                    v0 += o.x; v1 += o.y;
                }
                if (SPLITOUT) {
                    __nv_bfloat16 h0, l0, h1, l1;
                    split2(v0, h0, l0); split2(v1, h1, l1);
                    *reinterpret_cast<__nv_bfloat162*>(Oh + (size_t)m * N + n) =
                        __nv_bfloat162{h0, h1};
                    *reinterpret_cast<__nv_bfloat162*>(Ol + (size_t)m * N + n) =
                        __nv_bfloat162{l0, l1};
                } else {
                    *reinterpret_cast<float2*>(C + (size_t)m * N + n) =
                        make_float2(v0, v1);
                }
            }
        }
    }
}

constexpr int SM_128 = GC<128, 3>::SMEM;   // 113664
constexpr int SM_64  = GC<64,  4>::SMEM;   // 110592

// ---------------- launch ----------------
extern "C" void kernel_launch(void* const* d_in, const int* in_sizes, int n_in,
                              void* d_out, int out_size) {
    const int*   node_idx  = (const int*)  d_in[0];
    const int*   edge_idx  = (const int*)  d_in[1];
    const float* edge_w    = (const float*)d_in[2];
    const float* frozen    = (const float*)d_in[3];
    const float* W_root    = (const float*)d_in[4];
    const float* W_nbr     = (const float*)d_in[5];
    const float* b_mp      = (const float*)d_in[6];
    const float* W_post    = (const float*)d_in[7];
    const float* b_post    = (const float*)d_in[8];
    const float* fallback  = (const float*)d_in[9];
    const float* W_in      = (const float*)d_in[10];
    const float* b_in      = (const float*)d_in[11];
    const float* ln_g      = (const float*)d_in[12];
    const float* ln_b      = (const float*)d_in[13];
    const float* W1        = (const float*)d_in[14];
    const float* b1        = (const float*)d_in[15];
    const float* W2        = (const float*)d_in[16];
    const float* W_bil     = (const float*)d_in[17];
    const float* out_emb   = (const float*)d_in[18];
    float*       logits    = (float*)d_out;

    float *p_h;
    cudaGetSymbolAddress((void**)&p_h, g_h);
    __nv_bfloat16 *p_perth, *p_pertl, *p_xnh, *p_xnl, *p_acth, *p_actl;
    __nv_bfloat16 *p_hsh, *p_hsl, *p_projh, *p_projl;
    __nv_bfloat16 *p_Winh, *p_Winl, *p_W1h, *p_W1l, *p_W2h, *p_W2l;
    __nv_bfloat16 *p_bilh, *p_bill, *p_oeh, *p_oel;
    cudaGetSymbolAddress((void**)&p_perth, g_perth);
    cudaGetSymbolAddress((void**)&p_pertl, g_pertl);
    cudaGetSymbolAddress((void**)&p_xnh,  g_xnh);
    cudaGetSymbolAddress((void**)&p_xnl,  g_xnl);
    cudaGetSymbolAddress((void**)&p_acth, g_acth);
    cudaGetSymbolAddress((void**)&p_actl, g_actl);
    cudaGetSymbolAddress((void**)&p_hsh,  g_hsh);
    cudaGetSymbolAddress((void**)&p_hsl,  g_hsl);
    cudaGetSymbolAddress((void**)&p_projh, g_projh);
    cudaGetSymbolAddress((void**)&p_projl, g_projl);
    cudaGetSymbolAddress((void**)&p_Winh, g_Winh);
    cudaGetSymbolAddress((void**)&p_Winl, g_Winl);
    cudaGetSymbolAddress((void**)&p_W1h,  g_W1h);
    cudaGetSymbolAddress((void**)&p_W1l,  g_W1l);
    cudaGetSymbolAddress((void**)&p_W2h,  g_W2h);
    cudaGetSymbolAddress((void**)&p_W2l,  g_W2l);
    cudaGetSymbolAddress((void**)&p_bilh, g_bilh);
    cudaGetSymbolAddress((void**)&p_bill, g_bill);
    cudaGetSymbolAddress((void**)&p_oeh,  g_oeh);
    cudaGetSymbolAddress((void**)&p_oel,  g_oel);

    cudaFuncSetAttribute(gemm_bf3<64,  4, true,  true,  false, false>,
        cudaFuncAttributeMaxDynamicSharedMemorySize, SM_64);
    cudaFuncSetAttribute(gemm_bf3<128, 3, true,  true,  true,  false>,
        cudaFuncAttributeMaxDynamicSharedMemorySize, SM_128);
    cudaFuncSetAttribute(gemm_bf3<64,  4, false, false, false, true>,
        cudaFuncAttributeMaxDynamicSharedMemorySize, SM_64);
    cudaFuncSetAttribute(gemm_bf3<64,  4, false, false, true,  true>,
        cudaFuncAttributeMaxDynamicSharedMemorySize, SM_64);
    cudaFuncSetAttribute(gemm_bf3<128, 3, false, false, true,  false>,
        cudaFuncAttributeMaxDynamicSharedMemorySize, SM_128);
    cudaFuncSetAttribute(gemm_bf3<128, 3, false, false, false, false>,
        cudaFuncAttributeMaxDynamicSharedMemorySize, SM_128);

    // --- graph phase (edge at launch index 3 for ncu) ---
    zero_kernel<<<512, 256>>>();                               // 0
    mark_kernel<<<(BATCH + 255) / 256, 256>>>(node_idx);       // 1
    fused_wc_kernel<<<GNN_DIM + 1 + 128, GNN_DIM>>>(           // 2
        W_root, W_nbr, W_post, b_mp, b_post, W_in);
    {
        int warps = (N_EDGES + 31) / 32;
        int blocks = (warps + 7) / 8;
        edge_kernel<<<blocks, 256>>>(edge_idx, edge_w, frozen);  // 3
    }
    pert_kernel<<<BATCH / 8, GNN_DIM>>>(node_idx, frozen, fallback);  // 4

    // h = gelu(pert @ W_in + b_in)   [BM=64, 4-stage: 4x32 = 128 CTAs]
    {
        dim3 grid(HEAD_DIM / BN, BATCH / 64);
        gemm_bf3<64, 4, true, true, false, false><<<grid, 256, SM_64>>>(
            BATCH, HEAD_DIM, HEAD_DIM, GNN_DIM, p_perth, p_pertl, p_Winh, p_Winl,
            b_in, p_h, nullptr, nullptr);
    }

    // remaining weight splits
    split_kernel<<<2048, 256>>>(W1,    p_W1h,  p_W1l,  N_RES * HEAD_DIM * FF_DIM / 4);
    split_kernel<<<2048, 256>>>(W2,    p_W2h,  p_W2l,  N_RES * FF_DIM * HEAD_DIM / 4);
    split_kernel<<<512, 256>>>(W_bil,  p_bilh, p_bill, HEAD_DIM * BIL_DIM / 4);
    tsplit_oe<<<dim3(OE_PAD / 32, HEAD_DIM / 32), dim3(32, 8)>>>(out_emb, p_oeh, p_oel);

    for (int i = 0; i < N_RES; i++) {
        ln_kernel<<<BATCH, 128>>>(p_h, ln_g + (size_t)i * HEAD_DIM,
                                  ln_b + (size_t)i * HEAD_DIM);
        // W1: N=2048, 16x16 = 256 CTAs, BM=128 3-stage
        dim3 g1(FF_DIM / BN, BATCH / 128);
        gemm_bf3<128, 3, true, true, true, false><<<g1, 256, SM_128>>>(
            BATCH, FF_DIM, FF_DIM, HEAD_DIM, p_xnh, p_xnl,
            p_W1h + (size_t)i * HEAD_DIM * FF_DIM, p_W1l + (size_t)i * HEAD_DIM * FF_DIM,
            b1 + (size_t)i * FF_DIM, nullptr, p_acth, p_actl);
        // W2: N=512, BM=64 4-stage: 4x32 = 128 CTAs
        dim3 g2(HEAD_DIM / BN, BATCH / 64);
        if (i < N_RES - 1) {
            gemm_bf3<64, 4, false, false, false, true><<<g2, 256, SM_64>>>(
                BATCH, HEAD_DIM, HEAD_DIM, FF_DIM, p_acth, p_actl,
                p_W2h + (size_t)i * FF_DIM * HEAD_DIM, p_W2l + (size_t)i * FF_DIM * HEAD_DIM,
                nullptr, p_h, nullptr, nullptr);
        } else {
            gemm_bf3<64, 4, false, false, true, true><<<g2, 256, SM_64>>>(
                BATCH, HEAD_DIM, HEAD_DIM, FF_DIM, p_acth, p_actl,
                p_W2h + (size_t)i * FF_DIM * HEAD_DIM, p_W2l + (size_t)i * FF_DIM * HEAD_DIM,
                nullptr, p_h, p_hsh, p_hsl);
        }
    }
    // proj = h @ W_bil (split output): 12x16 = 192 CTAs
    {
        dim3 grid(BIL_DIM / BN, BATCH / 128);
        gemm_bf3<128, 3, false, false, true, false><<<grid, 256, SM_128>>>(
            BATCH, BIL_DIM, BIL_DIM, HEAD_DIM, p_hsh, p_hsl, p_bilh, p_bill,
            nullptr, nullptr, p_projh, p_projl);
    }
    // logits = proj @ oeT (padded ldb): 52x48 = 2496 CTAs, now 3-stage non-T
    {
        dim3 grid((N_GENES + BN - 1) / BN, (BATCH * N_CLASSES) / 128);
        gemm_bf3<128, 3, false, false, false, false><<<grid, 256, SM_128>>>(
            BATCH * N_CLASSES, N_GENES, OE_PAD, HEAD_DIM, p_projh, p_projl,
            p_oeh, p_oel, nullptr, logits, nullptr, nullptr);
    }
}